// round 2
// baseline (speedup 1.0000x reference)
#include <cuda_runtime.h>
#include <math.h>

// Problem constants (fixed shapes from reference)
#define B_   8
#define C_   512
#define N_   3136   // 56*56
#define IC_  256
#define ROWS_TOTAL (B_ * N_)   // 25088

// ---------------------------------------------------------------------------
// Scratch (static __device__ allocations; no cudaMalloc allowed)
// ---------------------------------------------------------------------------
__device__ float  g_Q [(size_t)B_ * N_ * IC_];
__device__ float  g_K [(size_t)B_ * N_ * IC_];
__device__ float  g_V [(size_t)B_ * N_ * IC_];
__device__ float  g_S [(size_t)B_ * N_ * N_];    // 314.7 MB attention logits/probs
__device__ float  g_y1[(size_t)B_ * N_ * IC_];
__device__ float  g_y2[(size_t)B_ * N_ * C_];
__device__ double g_sum[C_];
__device__ double g_sumsq[C_];

// ---------------------------------------------------------------------------
// Generic tiled GEMM:  C[m,n] = sum_k A[m,k]*B[k,n] (+ bias[n])
// BM=BN=64, BK=16, 128 threads, 8x4 micro-tile per thread.
// A_CONTIG_M: A contiguous in m (col-major view)  -> direct coalesced load
//             else A contiguous in k (row-major)  -> transpose on SMEM store
// B_CONTIG_N: B contiguous in n                   -> direct coalesced load
//             else B contiguous in k              -> transpose on SMEM store
// All launch shapes divide tiles exactly; no bounds checks.
// ---------------------------------------------------------------------------
constexpr int BM = 64, BN = 64, BK = 16;
constexpr int ASTR = BM + 4;   // padded stride (float) keeps float4 16B-aligned
constexpr int BSTR = BN + 4;

template<bool A_CONTIG_M, bool B_CONTIG_N, bool HAS_BIAS>
__global__ __launch_bounds__(128) void gemm_k(
    const float* __restrict__ A, const float* __restrict__ Bm,
    const float* __restrict__ bias, float* __restrict__ Cc,
    int K, int sAm, int sAk, int sBk, int sBn, int ldc,
    long long batA, long long batB, long long batC)
{
    A  += (long long)blockIdx.z * batA;
    Bm += (long long)blockIdx.z * batB;
    Cc += (long long)blockIdx.z * batC;

    const int m0 = blockIdx.x * BM;
    const int n0 = blockIdx.y * BN;
    const int tid = threadIdx.x;
    const int tx = tid & 15;       // 16 threads in n
    const int ty = tid >> 4;       // 8 threads in m

    __shared__ float As[BK * ASTR];
    __shared__ float Bs[BK * BSTR];

    float acc[8][4];
    #pragma unroll
    for (int i = 0; i < 8; i++)
        #pragma unroll
        for (int j = 0; j < 4; j++) acc[i][j] = 0.0f;

    for (int k0 = 0; k0 < K; k0 += BK) {
        // ---- load A tile into As[k][m] ----
        if (A_CONTIG_M) {
            #pragma unroll
            for (int it = 0; it < 2; it++) {
                int lin = tid + it * 128;           // 256 float4 = 64x16
                int kk = lin >> 4;
                int m4 = (lin & 15) << 2;
                float4 v = *(const float4*)(A + (long long)(k0 + kk) * sAk + (m0 + m4));
                *(float4*)(&As[kk * ASTR + m4]) = v;
            }
        } else {
            #pragma unroll
            for (int it = 0; it < 2; it++) {
                int lin = tid + it * 128;
                int mm = lin >> 2;
                int k4 = (lin & 3) << 2;
                float4 v = *(const float4*)(A + (long long)(m0 + mm) * sAm + (k0 + k4));
                As[(k4 + 0) * ASTR + mm] = v.x;
                As[(k4 + 1) * ASTR + mm] = v.y;
                As[(k4 + 2) * ASTR + mm] = v.z;
                As[(k4 + 3) * ASTR + mm] = v.w;
            }
        }
        // ---- load B tile into Bs[k][n] ----
        if (B_CONTIG_N) {
            #pragma unroll
            for (int it = 0; it < 2; it++) {
                int lin = tid + it * 128;
                int kk = lin >> 4;
                int n4 = (lin & 15) << 2;
                float4 v = *(const float4*)(Bm + (long long)(k0 + kk) * sBk + (n0 + n4));
                *(float4*)(&Bs[kk * BSTR + n4]) = v;
            }
        } else {
            #pragma unroll
            for (int it = 0; it < 2; it++) {
                int lin = tid + it * 128;
                int nn = lin >> 2;
                int k4 = (lin & 3) << 2;
                float4 v = *(const float4*)(Bm + (long long)(n0 + nn) * sBn + (k0 + k4));
                Bs[(k4 + 0) * BSTR + nn] = v.x;
                Bs[(k4 + 1) * BSTR + nn] = v.y;
                Bs[(k4 + 2) * BSTR + nn] = v.z;
                Bs[(k4 + 3) * BSTR + nn] = v.w;
            }
        }
        __syncthreads();

        #pragma unroll
        for (int kk = 0; kk < BK; kk++) {
            float4 a0 = *(const float4*)(&As[kk * ASTR + ty * 8]);
            float4 a1 = *(const float4*)(&As[kk * ASTR + ty * 8 + 4]);
            float4 b0 = *(const float4*)(&Bs[kk * BSTR + tx * 4]);
            float a[8] = {a0.x, a0.y, a0.z, a0.w, a1.x, a1.y, a1.z, a1.w};
            float b[4] = {b0.x, b0.y, b0.z, b0.w};
            #pragma unroll
            for (int i = 0; i < 8; i++)
                #pragma unroll
                for (int j = 0; j < 4; j++)
                    acc[i][j] += a[i] * b[j];
        }
        __syncthreads();
    }

    float bi[4] = {0.f, 0.f, 0.f, 0.f};
    if (HAS_BIAS) {
        #pragma unroll
        for (int j = 0; j < 4; j++) bi[j] = bias[n0 + tx * 4 + j];
    }
    #pragma unroll
    for (int i = 0; i < 8; i++) {
        float4 o;
        o.x = acc[i][0] + bi[0];
        o.y = acc[i][1] + bi[1];
        o.z = acc[i][2] + bi[2];
        o.w = acc[i][3] + bi[3];
        *(float4*)(Cc + (long long)(m0 + ty * 8 + i) * ldc + n0 + tx * 4) = o;
    }
}

// ---------------------------------------------------------------------------
// Row softmax over g_S: one block per row, row cached in SMEM (12.5 KB)
// ---------------------------------------------------------------------------
__global__ __launch_bounds__(256) void softmax_rows(float* __restrict__ S)
{
    __shared__ float buf[N_];
    __shared__ float red[256];
    float* row = S + (size_t)blockIdx.x * N_;
    const int tid = threadIdx.x;

    float m = -1e30f;
    for (int i = tid; i < N_; i += 256) {
        float v = row[i];
        buf[i] = v;
        m = fmaxf(m, v);
    }
    red[tid] = m;
    __syncthreads();
    for (int s = 128; s > 0; s >>= 1) {
        if (tid < s) red[tid] = fmaxf(red[tid], red[tid + s]);
        __syncthreads();
    }
    m = red[0];
    __syncthreads();

    float sum = 0.f;
    for (int i = tid; i < N_; i += 256) {
        float e = expf(buf[i] - m);
        buf[i] = e;
        sum += e;
    }
    red[tid] = sum;
    __syncthreads();
    for (int s = 128; s > 0; s >>= 1) {
        if (tid < s) red[tid] += red[tid + s];
        __syncthreads();
    }
    float inv = 1.0f / red[0];
    for (int i = tid; i < N_; i += 256) row[i] = buf[i] * inv;
}

// ---------------------------------------------------------------------------
// BN batch-statistics
// ---------------------------------------------------------------------------
__global__ void zero_stats()
{
    int t = threadIdx.x;   // 512 threads
    g_sum[t] = 0.0;
    g_sumsq[t] = 0.0;
}

// 196 blocks x 128 rows; 256 threads -> each thread owns channels {t, t+256}
__global__ __launch_bounds__(256) void bn_stats()
{
    const int tid = threadIdx.x;
    const int row0 = blockIdx.x * 128;
    const int c1 = tid, c2 = tid + 256;
    float s1 = 0.f, q1 = 0.f, s2 = 0.f, q2 = 0.f;
    for (int r = 0; r < 128; r++) {
        const float* p = g_y2 + (size_t)(row0 + r) * C_;
        float v1 = p[c1], v2 = p[c2];
        s1 += v1; q1 += v1 * v1;
        s2 += v2; q2 += v2 * v2;
    }
    atomicAdd(&g_sum[c1],   (double)s1);
    atomicAdd(&g_sumsq[c1], (double)q1);
    atomicAdd(&g_sum[c2],   (double)s2);
    atomicAdd(&g_sumsq[c2], (double)q2);
}

// ---------------------------------------------------------------------------
// BN normalize + residual + [B,N,C]->[B,C,N] transpose.  32x32 SMEM tiles.
// grid (98, 16, 8), block (32, 8)
// ---------------------------------------------------------------------------
__global__ __launch_bounds__(256) void bn_final(
    const float* __restrict__ x,
    const float* __restrict__ bn_w, const float* __restrict__ bn_b,
    float* __restrict__ out)
{
    __shared__ float t[32][33];
    const int b  = blockIdx.z;
    const int c0 = blockIdx.y * 32;
    const int n0 = blockIdx.x * 32;
    const int tx = threadIdx.x, ty = threadIdx.y;

    #pragma unroll
    for (int j = 0; j < 32; j += 8) {
        int n = n0 + ty + j;
        t[ty + j][tx] = g_y2[((size_t)(b * N_ + n)) * C_ + c0 + tx];
    }
    __syncthreads();

    const double cnt = (double)ROWS_TOTAL;
    #pragma unroll
    for (int j = 0; j < 32; j += 8) {
        int c = c0 + ty + j;
        double mean = g_sum[c] / cnt;
        double var  = g_sumsq[c] / cnt - mean * mean;
        float inv = (float)rsqrt(var + 1e-5);
        float w = bn_w[c], bb = bn_b[c];
        int n = n0 + tx;
        size_t oidx = ((size_t)b * C_ + c) * (size_t)N_ + n;
        float v = t[tx][ty + j];
        out[oidx] = (v - (float)mean) * inv * w + bb + x[oidx];
    }
}

// ---------------------------------------------------------------------------
// Launch
// ---------------------------------------------------------------------------
extern "C" void kernel_launch(void* const* d_in, const int* in_sizes, int n_in,
                              void* d_out, int out_size)
{
    const float* x       = (const float*)d_in[0];
    const float* theta_w = (const float*)d_in[1];
    const float* theta_b = (const float*)d_in[2];
    const float* phi_w   = (const float*)d_in[3];
    const float* phi_b   = (const float*)d_in[4];
    const float* gw      = (const float*)d_in[5];
    const float* gb      = (const float*)d_in[6];
    const float* wz_w    = (const float*)d_in[7];
    const float* wz_b    = (const float*)d_in[8];
    const float* bn_w    = (const float*)d_in[9];
    const float* bn_b    = (const float*)d_in[10];
    float* out = (float*)d_out;

    float *Q, *K, *V, *S, *y1, *y2;
    cudaGetSymbolAddress((void**)&Q,  g_Q);
    cudaGetSymbolAddress((void**)&K,  g_K);
    cudaGetSymbolAddress((void**)&V,  g_V);
    cudaGetSymbolAddress((void**)&S,  g_S);
    cudaGetSymbolAddress((void**)&y1, g_y1);
    cudaGetSymbolAddress((void**)&y2, g_y2);

    dim3 blk(128);

    zero_stats<<<1, 512>>>();

    // --- QKV projections: A = xf (col-major: x[c*N+n]), B = W (contig in k=c)
    // C[n,i] = sum_c x[c,n] * W[i,c] + b[i]
    {
        dim3 g(N_ / BM, IC_ / BN, B_);
        long long bA = (long long)C_ * N_, bC = (long long)N_ * IC_;
        gemm_k<true, false, true><<<g, blk>>>(x, theta_w, theta_b, Q,
            C_, /*sAm*/1, /*sAk*/N_, /*sBk*/1, /*sBn*/C_, /*ldc*/IC_, bA, 0, bC);
        gemm_k<true, false, true><<<g, blk>>>(x, phi_w, phi_b, K,
            C_, 1, N_, 1, C_, IC_, bA, 0, bC);
        gemm_k<true, false, true><<<g, blk>>>(x, gw, gb, V,
            C_, 1, N_, 1, C_, IC_, bA, 0, bC);
    }

    // --- S = Q * K^T   (A row-major, B contig in k)
    {
        dim3 g(N_ / BM, N_ / BN, B_);
        gemm_k<false, false, false><<<g, blk>>>(Q, K, nullptr, S,
            IC_, /*sAm*/IC_, /*sAk*/1, /*sBk*/1, /*sBn*/IC_, /*ldc*/N_,
            (long long)N_ * IC_, (long long)N_ * IC_, (long long)N_ * N_);
    }

    // --- softmax over rows of S
    softmax_rows<<<B_ * N_, 256>>>(S);

    // --- y1 = P * V   (A row-major, B row-major/contig-n)
    {
        dim3 g(N_ / BM, IC_ / BN, B_);
        gemm_k<false, true, false><<<g, blk>>>(S, V, nullptr, y1,
            N_, /*sAm*/N_, /*sAk*/1, /*sBk*/IC_, /*sBn*/1, /*ldc*/IC_,
            (long long)N_ * N_, (long long)N_ * IC_, (long long)N_ * IC_);
    }

    // --- y2 = y1 * Wz^T + b   (A row-major, B contig in k=i)
    {
        dim3 g(N_ / BM, C_ / BN, B_);
        gemm_k<false, false, true><<<g, blk>>>(y1, wz_w, wz_b, y2,
            IC_, /*sAm*/IC_, /*sAk*/1, /*sBk*/1, /*sBn*/IC_, /*ldc*/C_,
            (long long)N_ * IC_, 0, (long long)N_ * C_);
    }

    // --- BN stats + normalize + residual + transpose to [B,C,H,W]
    bn_stats<<<196, 256>>>();
    bn_final<<<dim3(N_ / 32, C_ / 32, B_), dim3(32, 8)>>>(x, bn_w, bn_b, out);
}

// round 3
// speedup vs baseline: 1.7378x; 1.7378x over previous
#include <cuda_runtime.h>
#include <math.h>
#include <stdint.h>

// Problem constants (fixed shapes from reference)
#define B_   8
#define C_   512
#define N_   3136   // 56*56
#define IC_  256
#define ROWS_TOTAL (B_ * N_)   // 25088

// ---------------------------------------------------------------------------
// Scratch
// ---------------------------------------------------------------------------
__device__ float  g_Q [(size_t)B_ * N_ * IC_];
__device__ float  g_K [(size_t)B_ * N_ * IC_];
__device__ float  g_V [(size_t)B_ * N_ * IC_];
__device__ float  g_S [(size_t)B_ * N_ * N_];
__device__ float  g_y1[(size_t)B_ * N_ * IC_];
__device__ float  g_y2[(size_t)B_ * N_ * C_];
__device__ double g_sum[C_];
__device__ double g_sumsq[C_];

// ---------------------------------------------------------------------------
// tf32 helpers
// ---------------------------------------------------------------------------
__device__ __forceinline__ uint32_t f2tf32(float x) {
    uint32_t u;
    asm("cvt.rna.tf32.f32 %0, %1;" : "=r"(u) : "f"(x));
    return u;
}

__device__ __forceinline__ void mma_tf32(float& d0, float& d1, float& d2, float& d3,
                                         uint32_t a0, uint32_t a1, uint32_t a2, uint32_t a3,
                                         uint32_t b0, uint32_t b1) {
    asm volatile(
        "mma.sync.aligned.m16n8k8.row.col.f32.tf32.tf32.f32 "
        "{%0,%1,%2,%3}, {%4,%5,%6,%7}, {%8,%9}, {%0,%1,%2,%3};\n"
        : "+f"(d0), "+f"(d1), "+f"(d2), "+f"(d3)
        : "r"(a0), "r"(a1), "r"(a2), "r"(a3), "r"(b0), "r"(b1));
}

// ---------------------------------------------------------------------------
// Tensor-core GEMM:  C[m,n] = sum_k A[m,k]*B[k,n] (+ bias[n])
// BM=BN=64, BK=16, 128 threads (4 warps in 2x2), warp tile 32x32 via
// m16n8k8 tf32 mma (mt=2 x nt=4 tiles).
//
// A_K_CONTIG: A contiguous in k (row-major)  -> SMEM As[m][k], stride 20
//       else: A contiguous in m (col-major)  -> SMEM As[k][m], stride 72
// B_K_CONTIG: B contiguous in k              -> SMEM Bs[n][k], stride 20
//       else: B contiguous in n              -> SMEM Bs[k][n], stride 72
// Strides 20 (mod 32 = 4*...) and 72 (mod 32 = 8) make all fragment LDS
// patterns bank-conflict-free. tf32 rounding (cvt.rna) happens at SMEM store.
// All shapes divide tiles exactly; no bounds checks.
// ---------------------------------------------------------------------------
constexpr int BM = 64, BN = 64, BK = 16;
constexpr int S_RK = BK + 4;   // 20: [x][k] layout stride
constexpr int S_KM = BM + 8;   // 72: [k][x] layout stride

template<bool A_K_CONTIG, bool B_K_CONTIG, bool HAS_BIAS>
__global__ __launch_bounds__(128) void gemm_tc(
    const float* __restrict__ A, const float* __restrict__ Bm,
    const float* __restrict__ bias, float* __restrict__ Cc,
    int K, int sA, int sB, int ldc,
    long long batA, long long batB, long long batC)
{
    A  += (long long)blockIdx.z * batA;
    Bm += (long long)blockIdx.z * batB;
    Cc += (long long)blockIdx.z * batC;

    const int m0 = blockIdx.x * BM;
    const int n0 = blockIdx.y * BN;
    const int tid = threadIdx.x;
    const int w   = tid >> 5;
    const int lane = tid & 31;
    const int gid = lane >> 2;     // 0..7
    const int tig = lane & 3;      // 0..3
    const int wm = (w & 1) * 32;   // warp row offset
    const int wn = (w >> 1) * 32;  // warp col offset

    __shared__ uint32_t As[BM * S_RK];   // 1280 words, covers both layouts
    __shared__ uint32_t Bs[BN * S_RK];

    float acc[2][4][4];
    #pragma unroll
    for (int i = 0; i < 2; i++)
        #pragma unroll
        for (int j = 0; j < 4; j++)
            #pragma unroll
            for (int r = 0; r < 4; r++) acc[i][j][r] = 0.0f;

    for (int k0 = 0; k0 < K; k0 += BK) {
        // ---- load A tile ----
        if (A_K_CONTIG) {
            #pragma unroll
            for (int it = 0; it < 2; it++) {
                int lin = tid + it * 128;        // 256 float4 = 64 x 16
                int mm = lin >> 2;
                int k4 = (lin & 3) << 2;
                float4 v = *(const float4*)(A + (long long)(m0 + mm) * sA + (k0 + k4));
                uint4 u = make_uint4(f2tf32(v.x), f2tf32(v.y), f2tf32(v.z), f2tf32(v.w));
                *(uint4*)(&As[mm * S_RK + k4]) = u;
            }
        } else {
            #pragma unroll
            for (int it = 0; it < 2; it++) {
                int lin = tid + it * 128;        // 16 x 64
                int kk = lin >> 4;
                int m4 = (lin & 15) << 2;
                float4 v = *(const float4*)(A + (long long)(k0 + kk) * sA + (m0 + m4));
                uint4 u = make_uint4(f2tf32(v.x), f2tf32(v.y), f2tf32(v.z), f2tf32(v.w));
                *(uint4*)(&As[kk * S_KM + m4]) = u;
            }
        }
        // ---- load B tile ----
        if (B_K_CONTIG) {
            #pragma unroll
            for (int it = 0; it < 2; it++) {
                int lin = tid + it * 128;
                int nn = lin >> 2;
                int k4 = (lin & 3) << 2;
                float4 v = *(const float4*)(Bm + (long long)(n0 + nn) * sB + (k0 + k4));
                uint4 u = make_uint4(f2tf32(v.x), f2tf32(v.y), f2tf32(v.z), f2tf32(v.w));
                *(uint4*)(&Bs[nn * S_RK + k4]) = u;
            }
        } else {
            #pragma unroll
            for (int it = 0; it < 2; it++) {
                int lin = tid + it * 128;
                int kk = lin >> 4;
                int n4 = (lin & 15) << 2;
                float4 v = *(const float4*)(Bm + (long long)(k0 + kk) * sB + (n0 + n4));
                uint4 u = make_uint4(f2tf32(v.x), f2tf32(v.y), f2tf32(v.z), f2tf32(v.w));
                *(uint4*)(&Bs[kk * S_KM + n4]) = u;
            }
        }
        __syncthreads();

        #pragma unroll
        for (int ks = 0; ks < 2; ks++) {
            const int kk = ks * 8;
            // A fragments for 2 m-tiles
            uint32_t af[2][4];
            #pragma unroll
            for (int i = 0; i < 2; i++) {
                int row = wm + i * 16;
                if (A_K_CONTIG) {
                    af[i][0] = As[(row + gid)     * S_RK + kk + tig];
                    af[i][1] = As[(row + gid + 8) * S_RK + kk + tig];
                    af[i][2] = As[(row + gid)     * S_RK + kk + tig + 4];
                    af[i][3] = As[(row + gid + 8) * S_RK + kk + tig + 4];
                } else {
                    af[i][0] = As[(kk + tig)     * S_KM + row + gid];
                    af[i][1] = As[(kk + tig)     * S_KM + row + gid + 8];
                    af[i][2] = As[(kk + tig + 4) * S_KM + row + gid];
                    af[i][3] = As[(kk + tig + 4) * S_KM + row + gid + 8];
                }
            }
            // B fragments for 4 n-tiles
            uint32_t bf[4][2];
            #pragma unroll
            for (int j = 0; j < 4; j++) {
                int col = wn + j * 8;
                if (B_K_CONTIG) {
                    bf[j][0] = Bs[(col + gid) * S_RK + kk + tig];
                    bf[j][1] = Bs[(col + gid) * S_RK + kk + tig + 4];
                } else {
                    bf[j][0] = Bs[(kk + tig)     * S_KM + col + gid];
                    bf[j][1] = Bs[(kk + tig + 4) * S_KM + col + gid];
                }
            }
            #pragma unroll
            for (int i = 0; i < 2; i++)
                #pragma unroll
                for (int j = 0; j < 4; j++)
                    mma_tf32(acc[i][j][0], acc[i][j][1], acc[i][j][2], acc[i][j][3],
                             af[i][0], af[i][1], af[i][2], af[i][3],
                             bf[j][0], bf[j][1]);
        }
        __syncthreads();
    }

    // ---- epilogue ----
    #pragma unroll
    for (int i = 0; i < 2; i++) {
        int grow = m0 + wm + i * 16 + gid;
        #pragma unroll
        for (int j = 0; j < 4; j++) {
            int gcol = n0 + wn + j * 8 + tig * 2;
            float b0v = 0.f, b1v = 0.f;
            if (HAS_BIAS) { b0v = bias[gcol]; b1v = bias[gcol + 1]; }
            float2 o0 = make_float2(acc[i][j][0] + b0v, acc[i][j][1] + b1v);
            float2 o1 = make_float2(acc[i][j][2] + b0v, acc[i][j][3] + b1v);
            *(float2*)(Cc + (long long)grow * ldc + gcol)       = o0;
            *(float2*)(Cc + (long long)(grow + 8) * ldc + gcol) = o1;
        }
    }
}

// ---------------------------------------------------------------------------
// Row softmax over g_S: one block per row, row cached in SMEM
// ---------------------------------------------------------------------------
__global__ __launch_bounds__(256) void softmax_rows(float* __restrict__ S)
{
    __shared__ float buf[N_];
    __shared__ float red[256];
    float* row = S + (size_t)blockIdx.x * N_;
    const int tid = threadIdx.x;

    float m = -1e30f;
    for (int i = tid; i < N_; i += 256) {
        float v = row[i];
        buf[i] = v;
        m = fmaxf(m, v);
    }
    red[tid] = m;
    __syncthreads();
    for (int s = 128; s > 0; s >>= 1) {
        if (tid < s) red[tid] = fmaxf(red[tid], red[tid + s]);
        __syncthreads();
    }
    m = red[0];
    __syncthreads();

    float sum = 0.f;
    for (int i = tid; i < N_; i += 256) {
        float e = expf(buf[i] - m);
        buf[i] = e;
        sum += e;
    }
    red[tid] = sum;
    __syncthreads();
    for (int s = 128; s > 0; s >>= 1) {
        if (tid < s) red[tid] += red[tid + s];
        __syncthreads();
    }
    float inv = 1.0f / red[0];
    for (int i = tid; i < N_; i += 256) row[i] = buf[i] * inv;
}

// ---------------------------------------------------------------------------
// BN batch-statistics
// ---------------------------------------------------------------------------
__global__ void zero_stats()
{
    int t = threadIdx.x;   // 512 threads
    g_sum[t] = 0.0;
    g_sumsq[t] = 0.0;
}

__global__ __launch_bounds__(256) void bn_stats()
{
    const int tid = threadIdx.x;
    const int row0 = blockIdx.x * 128;
    const int c1 = tid, c2 = tid + 256;
    float s1 = 0.f, q1 = 0.f, s2 = 0.f, q2 = 0.f;
    for (int r = 0; r < 128; r++) {
        const float* p = g_y2 + (size_t)(row0 + r) * C_;
        float v1 = p[c1], v2 = p[c2];
        s1 += v1; q1 += v1 * v1;
        s2 += v2; q2 += v2 * v2;
    }
    atomicAdd(&g_sum[c1],   (double)s1);
    atomicAdd(&g_sumsq[c1], (double)q1);
    atomicAdd(&g_sum[c2],   (double)s2);
    atomicAdd(&g_sumsq[c2], (double)q2);
}

// ---------------------------------------------------------------------------
// BN normalize + residual + [B,N,C]->[B,C,N] transpose
// ---------------------------------------------------------------------------
__global__ __launch_bounds__(256) void bn_final(
    const float* __restrict__ x,
    const float* __restrict__ bn_w, const float* __restrict__ bn_b,
    float* __restrict__ out)
{
    __shared__ float t[32][33];
    const int b  = blockIdx.z;
    const int c0 = blockIdx.y * 32;
    const int n0 = blockIdx.x * 32;
    const int tx = threadIdx.x, ty = threadIdx.y;

    #pragma unroll
    for (int j = 0; j < 32; j += 8) {
        int n = n0 + ty + j;
        t[ty + j][tx] = g_y2[((size_t)(b * N_ + n)) * C_ + c0 + tx];
    }
    __syncthreads();

    const double cnt = (double)ROWS_TOTAL;
    #pragma unroll
    for (int j = 0; j < 32; j += 8) {
        int c = c0 + ty + j;
        double mean = g_sum[c] / cnt;
        double var  = g_sumsq[c] / cnt - mean * mean;
        float inv = (float)rsqrt(var + 1e-5);
        float w = bn_w[c], bb = bn_b[c];
        int n = n0 + tx;
        size_t oidx = ((size_t)b * C_ + c) * (size_t)N_ + n;
        float v = t[tx][ty + j];
        out[oidx] = (v - (float)mean) * inv * w + bb + x[oidx];
    }
}

// ---------------------------------------------------------------------------
// Launch
// ---------------------------------------------------------------------------
extern "C" void kernel_launch(void* const* d_in, const int* in_sizes, int n_in,
                              void* d_out, int out_size)
{
    const float* x       = (const float*)d_in[0];
    const float* theta_w = (const float*)d_in[1];
    const float* theta_b = (const float*)d_in[2];
    const float* phi_w   = (const float*)d_in[3];
    const float* phi_b   = (const float*)d_in[4];
    const float* gw      = (const float*)d_in[5];
    const float* gb      = (const float*)d_in[6];
    const float* wz_w    = (const float*)d_in[7];
    const float* wz_b    = (const float*)d_in[8];
    const float* bn_w    = (const float*)d_in[9];
    const float* bn_b    = (const float*)d_in[10];
    float* out = (float*)d_out;

    float *Q, *K, *V, *S, *y1, *y2;
    cudaGetSymbolAddress((void**)&Q,  g_Q);
    cudaGetSymbolAddress((void**)&K,  g_K);
    cudaGetSymbolAddress((void**)&V,  g_V);
    cudaGetSymbolAddress((void**)&S,  g_S);
    cudaGetSymbolAddress((void**)&y1, g_y1);
    cudaGetSymbolAddress((void**)&y2, g_y2);

    dim3 blk(128);

    zero_stats<<<1, 512>>>();

    // --- QKV projections: C[n,i] = sum_c x[c*N+n] * W[i*C+c] + b[i]
    // A = x: contig in m (col-major), sA = N_.  B = W: contig in k, sB = C_.
    {
        dim3 g(N_ / BM, IC_ / BN, B_);
        long long bA = (long long)C_ * N_, bC = (long long)N_ * IC_;
        gemm_tc<false, true, true><<<g, blk>>>(x, theta_w, theta_b, Q,
            C_, /*sA*/N_, /*sB*/C_, /*ldc*/IC_, bA, 0, bC);
        gemm_tc<false, true, true><<<g, blk>>>(x, phi_w, phi_b, K,
            C_, N_, C_, IC_, bA, 0, bC);
        gemm_tc<false, true, true><<<g, blk>>>(x, gw, gb, V,
            C_, N_, C_, IC_, bA, 0, bC);
    }

    // --- S = Q * K^T : A contig in k (sA=IC), B contig in k (sB=IC)
    {
        dim3 g(N_ / BM, N_ / BN, B_);
        gemm_tc<true, true, false><<<g, blk>>>(Q, K, nullptr, S,
            IC_, IC_, IC_, N_,
            (long long)N_ * IC_, (long long)N_ * IC_, (long long)N_ * N_);
    }

    // --- softmax over rows of S
    softmax_rows<<<B_ * N_, 256>>>(S);

    // --- y1 = P * V : A contig in k (sA=N_), B contig in n (sB=IC_)
    {
        dim3 g(N_ / BM, IC_ / BN, B_);
        gemm_tc<true, false, false><<<g, blk>>>(S, V, nullptr, y1,
            N_, N_, IC_, IC_,
            (long long)N_ * N_, (long long)N_ * IC_, (long long)N_ * IC_);
    }

    // --- y2 = y1 * Wz^T + b : A contig in k (sA=IC), B contig in k (sB=IC)
    {
        dim3 g(N_ / BM, C_ / BN, B_);
        gemm_tc<true, true, true><<<g, blk>>>(y1, wz_w, wz_b, y2,
            IC_, IC_, IC_, C_,
            (long long)N_ * IC_, 0, (long long)N_ * C_);
    }

    // --- BN stats + normalize + residual + transpose
    bn_stats<<<196, 256>>>();
    bn_final<<<dim3(N_ / 32, C_ / 32, B_), dim3(32, 8)>>>(x, bn_w, bn_b, out);
}

// round 4
// speedup vs baseline: 1.8169x; 1.0455x over previous
#include <cuda_runtime.h>
#include <math.h>
#include <stdint.h>

// Problem constants
#define B_   8
#define C_   512
#define N_   3136   // 56*56
#define NP_  3200   // N padded to multiple of 128
#define IC_  256
#define ROWS_TOTAL (B_ * N_)   // 25088

// ---------------------------------------------------------------------------
// Scratch (padded row dims where a GEMM m/n spans N)
// ---------------------------------------------------------------------------
__device__ float  g_Q [(size_t)B_ * NP_ * IC_];
__device__ float  g_K [(size_t)B_ * NP_ * IC_];
__device__ float  g_V [(size_t)B_ * NP_ * IC_];
__device__ float  g_S [(size_t)B_ * NP_ * NP_];   // 327.7 MB
__device__ float  g_y1[(size_t)B_ * NP_ * IC_];
__device__ float  g_y2[(size_t)B_ * N_ * C_];
__device__ double g_sum[C_];
__device__ double g_sumsq[C_];

// ---------------------------------------------------------------------------
// tf32 helpers
// ---------------------------------------------------------------------------
__device__ __forceinline__ uint32_t f2tf32(float x) {
    uint32_t u;
    asm("cvt.rna.tf32.f32 %0, %1;" : "=r"(u) : "f"(x));
    return u;
}
__device__ __forceinline__ uint4 cvt4(float4 v) {
    return make_uint4(f2tf32(v.x), f2tf32(v.y), f2tf32(v.z), f2tf32(v.w));
}
__device__ __forceinline__ void mma_tf32(float& d0, float& d1, float& d2, float& d3,
                                         uint32_t a0, uint32_t a1, uint32_t a2, uint32_t a3,
                                         uint32_t b0, uint32_t b1) {
    asm volatile(
        "mma.sync.aligned.m16n8k8.row.col.f32.tf32.tf32.f32 "
        "{%0,%1,%2,%3}, {%4,%5,%6,%7}, {%8,%9}, {%0,%1,%2,%3};\n"
        : "+f"(d0), "+f"(d1), "+f"(d2), "+f"(d3)
        : "r"(a0), "r"(a1), "r"(a2), "r"(a3), "r"(b0), "r"(b1));
}

// ===========================================================================
// Kernel 1: 64x64x16 tensor-core GEMM (QKV projections, y2) — proven R2 code
// ===========================================================================
constexpr int BM = 64, BN = 64, BK = 16;
constexpr int S_RK = BK + 4;   // 20
constexpr int S_KM = BM + 8;   // 72

template<bool A_K_CONTIG, bool B_K_CONTIG, bool HAS_BIAS>
__global__ __launch_bounds__(128) void gemm_tc(
    const float* __restrict__ A, const float* __restrict__ Bm,
    const float* __restrict__ bias, float* __restrict__ Cc,
    int K, int sA, int sB, int ldc,
    long long batA, long long batB, long long batC)
{
    A  += (long long)blockIdx.z * batA;
    Bm += (long long)blockIdx.z * batB;
    Cc += (long long)blockIdx.z * batC;

    const int m0 = blockIdx.x * BM;
    const int n0 = blockIdx.y * BN;
    const int tid = threadIdx.x;
    const int w   = tid >> 5;
    const int lane = tid & 31;
    const int gid = lane >> 2;
    const int tig = lane & 3;
    const int wm = (w & 1) * 32;
    const int wn = (w >> 1) * 32;

    __shared__ uint32_t As[BM * S_RK];
    __shared__ uint32_t Bs[BN * S_RK];

    float acc[2][4][4];
    #pragma unroll
    for (int i = 0; i < 2; i++)
        #pragma unroll
        for (int j = 0; j < 4; j++)
            #pragma unroll
            for (int r = 0; r < 4; r++) acc[i][j][r] = 0.0f;

    for (int k0 = 0; k0 < K; k0 += BK) {
        if (A_K_CONTIG) {
            #pragma unroll
            for (int it = 0; it < 2; it++) {
                int lin = tid + it * 128;
                int mm = lin >> 2;
                int k4 = (lin & 3) << 2;
                float4 v = *(const float4*)(A + (long long)(m0 + mm) * sA + (k0 + k4));
                *(uint4*)(&As[mm * S_RK + k4]) = cvt4(v);
            }
        } else {
            #pragma unroll
            for (int it = 0; it < 2; it++) {
                int lin = tid + it * 128;
                int kk = lin >> 4;
                int m4 = (lin & 15) << 2;
                float4 v = *(const float4*)(A + (long long)(k0 + kk) * sA + (m0 + m4));
                *(uint4*)(&As[kk * S_KM + m4]) = cvt4(v);
            }
        }
        if (B_K_CONTIG) {
            #pragma unroll
            for (int it = 0; it < 2; it++) {
                int lin = tid + it * 128;
                int nn = lin >> 2;
                int k4 = (lin & 3) << 2;
                float4 v = *(const float4*)(Bm + (long long)(n0 + nn) * sB + (k0 + k4));
                *(uint4*)(&Bs[nn * S_RK + k4]) = cvt4(v);
            }
        } else {
            #pragma unroll
            for (int it = 0; it < 2; it++) {
                int lin = tid + it * 128;
                int kk = lin >> 4;
                int n4 = (lin & 15) << 2;
                float4 v = *(const float4*)(Bm + (long long)(k0 + kk) * sB + (n0 + n4));
                *(uint4*)(&Bs[kk * S_KM + n4]) = cvt4(v);
            }
        }
        __syncthreads();

        #pragma unroll
        for (int ks = 0; ks < 2; ks++) {
            const int kk = ks * 8;
            uint32_t af[2][4];
            #pragma unroll
            for (int i = 0; i < 2; i++) {
                int row = wm + i * 16;
                if (A_K_CONTIG) {
                    af[i][0] = As[(row + gid)     * S_RK + kk + tig];
                    af[i][1] = As[(row + gid + 8) * S_RK + kk + tig];
                    af[i][2] = As[(row + gid)     * S_RK + kk + tig + 4];
                    af[i][3] = As[(row + gid + 8) * S_RK + kk + tig + 4];
                } else {
                    af[i][0] = As[(kk + tig)     * S_KM + row + gid];
                    af[i][1] = As[(kk + tig)     * S_KM + row + gid + 8];
                    af[i][2] = As[(kk + tig + 4) * S_KM + row + gid];
                    af[i][3] = As[(kk + tig + 4) * S_KM + row + gid + 8];
                }
            }
            uint32_t bf[4][2];
            #pragma unroll
            for (int j = 0; j < 4; j++) {
                int col = wn + j * 8;
                if (B_K_CONTIG) {
                    bf[j][0] = Bs[(col + gid) * S_RK + kk + tig];
                    bf[j][1] = Bs[(col + gid) * S_RK + kk + tig + 4];
                } else {
                    bf[j][0] = Bs[(kk + tig)     * S_KM + col + gid];
                    bf[j][1] = Bs[(kk + tig + 4) * S_KM + col + gid];
                }
            }
            #pragma unroll
            for (int i = 0; i < 2; i++)
                #pragma unroll
                for (int j = 0; j < 4; j++)
                    mma_tf32(acc[i][j][0], acc[i][j][1], acc[i][j][2], acc[i][j][3],
                             af[i][0], af[i][1], af[i][2], af[i][3],
                             bf[j][0], bf[j][1]);
        }
        __syncthreads();
    }

    #pragma unroll
    for (int i = 0; i < 2; i++) {
        int grow = m0 + wm + i * 16 + gid;
        #pragma unroll
        for (int j = 0; j < 4; j++) {
            int gcol = n0 + wn + j * 8 + tig * 2;
            float b0v = 0.f, b1v = 0.f;
            if (HAS_BIAS) { b0v = bias[gcol]; b1v = bias[gcol + 1]; }
            float2 o0 = make_float2(acc[i][j][0] + b0v, acc[i][j][1] + b1v);
            float2 o1 = make_float2(acc[i][j][2] + b0v, acc[i][j][3] + b1v);
            *(float2*)(Cc + (long long)grow * ldc + gcol)       = o0;
            *(float2*)(Cc + (long long)(grow + 8) * ldc + gcol) = o1;
        }
    }
}

// ===========================================================================
// Kernel 2: 128x128x16 double-buffered tensor-core GEMM (S = QK^T, y1 = PV)
// A is always k-contiguous. 256 threads = 8 warps (2m x 4n), warp tile 64x32.
// ===========================================================================
constexpr int BM2 = 128, BN2 = 128, BK2 = 16;
constexpr int SRK2 = BK2 + 4;    // 20  ([x][k] layout)
constexpr int SKN2 = BN2 + 8;    // 136 ([k][n] layout)
constexpr int SBUF = BM2 * SRK2; // 2560 words, covers both layouts

template<bool B_K_CONTIG, bool HAS_BIAS>
__global__ __launch_bounds__(256) void gemm_tc128(
    const float* __restrict__ A, const float* __restrict__ Bm,
    const float* __restrict__ bias, float* __restrict__ Cc,
    int K, int sA, int sB, int ldc,
    long long batA, long long batB, long long batC)
{
    A  += (long long)blockIdx.z * batA;
    Bm += (long long)blockIdx.z * batB;
    Cc += (long long)blockIdx.z * batC;

    const int m0 = blockIdx.x * BM2;
    const int n0 = blockIdx.y * BN2;
    const int tid = threadIdx.x;
    const int w   = tid >> 5;
    const int lane = tid & 31;
    const int gid = lane >> 2;
    const int tig = lane & 3;
    const int wm = (w & 1) * 64;      // 2 warps in m
    const int wn = (w >> 1) * 32;     // 4 warps in n

    __shared__ uint32_t As[2][SBUF];
    __shared__ uint32_t Bs[2][SBUF];

    float acc[4][4][4];
    #pragma unroll
    for (int i = 0; i < 4; i++)
        #pragma unroll
        for (int j = 0; j < 4; j++)
            #pragma unroll
            for (int r = 0; r < 4; r++) acc[i][j][r] = 0.0f;

    // per-thread load coordinates (2 float4 each for A and B)
    float4 ra[2], rb[2];

    // ---- prologue: load tile 0 into regs, store to buf 0 ----
    #pragma unroll
    for (int it = 0; it < 2; it++) {
        int lin = tid + it * 256;
        int mm = lin >> 2, k4 = (lin & 3) << 2;
        ra[it] = *(const float4*)(A + (long long)(m0 + mm) * sA + k4);
    }
    if (B_K_CONTIG) {
        #pragma unroll
        for (int it = 0; it < 2; it++) {
            int lin = tid + it * 256;
            int nn = lin >> 2, k4 = (lin & 3) << 2;
            rb[it] = *(const float4*)(Bm + (long long)(n0 + nn) * sB + k4);
        }
    } else {
        #pragma unroll
        for (int it = 0; it < 2; it++) {
            int lin = tid + it * 256;
            int kk = lin >> 5, n4 = (lin & 31) << 2;
            rb[it] = *(const float4*)(Bm + (long long)kk * sB + n0 + n4);
        }
    }
    #pragma unroll
    for (int it = 0; it < 2; it++) {
        int lin = tid + it * 256;
        int mm = lin >> 2, k4 = (lin & 3) << 2;
        *(uint4*)(&As[0][mm * SRK2 + k4]) = cvt4(ra[it]);
    }
    if (B_K_CONTIG) {
        #pragma unroll
        for (int it = 0; it < 2; it++) {
            int lin = tid + it * 256;
            int nn = lin >> 2, k4 = (lin & 3) << 2;
            *(uint4*)(&Bs[0][nn * SRK2 + k4]) = cvt4(rb[it]);
        }
    } else {
        #pragma unroll
        for (int it = 0; it < 2; it++) {
            int lin = tid + it * 256;
            int kk = lin >> 5, n4 = (lin & 31) << 2;
            *(uint4*)(&Bs[0][kk * SKN2 + n4]) = cvt4(rb[it]);
        }
    }
    __syncthreads();

    int buf = 0;
    for (int k0 = 0; k0 < K; k0 += BK2) {
        const bool nxt = (k0 + BK2 < K);
        // ---- prefetch next tile into registers ----
        if (nxt) {
            int kn = k0 + BK2;
            #pragma unroll
            for (int it = 0; it < 2; it++) {
                int lin = tid + it * 256;
                int mm = lin >> 2, k4 = (lin & 3) << 2;
                ra[it] = *(const float4*)(A + (long long)(m0 + mm) * sA + kn + k4);
            }
            if (B_K_CONTIG) {
                #pragma unroll
                for (int it = 0; it < 2; it++) {
                    int lin = tid + it * 256;
                    int nn = lin >> 2, k4 = (lin & 3) << 2;
                    rb[it] = *(const float4*)(Bm + (long long)(n0 + nn) * sB + kn + k4);
                }
            } else {
                #pragma unroll
                for (int it = 0; it < 2; it++) {
                    int lin = tid + it * 256;
                    int kk = lin >> 5, n4 = (lin & 31) << 2;
                    rb[it] = *(const float4*)(Bm + (long long)(kn + kk) * sB + n0 + n4);
                }
            }
        }
        // ---- compute current buffer ----
        const uint32_t* Ab = As[buf];
        const uint32_t* Bb = Bs[buf];
        #pragma unroll
        for (int ks = 0; ks < 2; ks++) {
            const int kk = ks * 8;
            uint32_t af[4][4];
            #pragma unroll
            for (int i = 0; i < 4; i++) {
                int row = wm + i * 16;
                af[i][0] = Ab[(row + gid)     * SRK2 + kk + tig];
                af[i][1] = Ab[(row + gid + 8) * SRK2 + kk + tig];
                af[i][2] = Ab[(row + gid)     * SRK2 + kk + tig + 4];
                af[i][3] = Ab[(row + gid + 8) * SRK2 + kk + tig + 4];
            }
            uint32_t bf[4][2];
            #pragma unroll
            for (int j = 0; j < 4; j++) {
                int col = wn + j * 8;
                if (B_K_CONTIG) {
                    bf[j][0] = Bb[(col + gid) * SRK2 + kk + tig];
                    bf[j][1] = Bb[(col + gid) * SRK2 + kk + tig + 4];
                } else {
                    bf[j][0] = Bb[(kk + tig)     * SKN2 + col + gid];
                    bf[j][1] = Bb[(kk + tig + 4) * SKN2 + col + gid];
                }
            }
            #pragma unroll
            for (int i = 0; i < 4; i++)
                #pragma unroll
                for (int j = 0; j < 4; j++)
                    mma_tf32(acc[i][j][0], acc[i][j][1], acc[i][j][2], acc[i][j][3],
                             af[i][0], af[i][1], af[i][2], af[i][3],
                             bf[j][0], bf[j][1]);
        }
        // ---- store prefetched tile into the other buffer ----
        if (nxt) {
            int ob = buf ^ 1;
            #pragma unroll
            for (int it = 0; it < 2; it++) {
                int lin = tid + it * 256;
                int mm = lin >> 2, k4 = (lin & 3) << 2;
                *(uint4*)(&As[ob][mm * SRK2 + k4]) = cvt4(ra[it]);
            }
            if (B_K_CONTIG) {
                #pragma unroll
                for (int it = 0; it < 2; it++) {
                    int lin = tid + it * 256;
                    int nn = lin >> 2, k4 = (lin & 3) << 2;
                    *(uint4*)(&Bs[ob][nn * SRK2 + k4]) = cvt4(rb[it]);
                }
            } else {
                #pragma unroll
                for (int it = 0; it < 2; it++) {
                    int lin = tid + it * 256;
                    int kk = lin >> 5, n4 = (lin & 31) << 2;
                    *(uint4*)(&Bs[ob][kk * SKN2 + n4]) = cvt4(rb[it]);
                }
            }
            __syncthreads();
            buf = ob;
        }
    }

    // ---- epilogue ----
    #pragma unroll
    for (int i = 0; i < 4; i++) {
        int grow = m0 + wm + i * 16 + gid;
        #pragma unroll
        for (int j = 0; j < 4; j++) {
            int gcol = n0 + wn + j * 8 + tig * 2;
            float b0v = 0.f, b1v = 0.f;
            if (HAS_BIAS) { b0v = bias[gcol]; b1v = bias[gcol + 1]; }
            float2 o0 = make_float2(acc[i][j][0] + b0v, acc[i][j][1] + b1v);
            float2 o1 = make_float2(acc[i][j][2] + b0v, acc[i][j][3] + b1v);
            *(float2*)(Cc + (long long)grow * ldc + gcol)       = o0;
            *(float2*)(Cc + (long long)(grow + 8) * ldc + gcol) = o1;
        }
    }
}

// ---------------------------------------------------------------------------
// Row softmax over padded S: grid (N_, B_); only cols [0, N_) touched.
// ---------------------------------------------------------------------------
__global__ __launch_bounds__(256) void softmax_rows(float* __restrict__ S)
{
    __shared__ float buf[N_];
    __shared__ float red[256];
    float* row = S + (size_t)blockIdx.y * NP_ * NP_ + (size_t)blockIdx.x * NP_;
    const int tid = threadIdx.x;

    float m = -1e30f;
    for (int i = tid; i < N_; i += 256) {
        float v = row[i];
        buf[i] = v;
        m = fmaxf(m, v);
    }
    red[tid] = m;
    __syncthreads();
    for (int s = 128; s > 0; s >>= 1) {
        if (tid < s) red[tid] = fmaxf(red[tid], red[tid + s]);
        __syncthreads();
    }
    m = red[0];
    __syncthreads();

    float sum = 0.f;
    for (int i = tid; i < N_; i += 256) {
        float e = expf(buf[i] - m);
        buf[i] = e;
        sum += e;
    }
    red[tid] = sum;
    __syncthreads();
    for (int s = 128; s > 0; s >>= 1) {
        if (tid < s) red[tid] += red[tid + s];
        __syncthreads();
    }
    float inv = 1.0f / red[0];
    for (int i = tid; i < N_; i += 256) row[i] = buf[i] * inv;
}

// ---------------------------------------------------------------------------
// BN batch-statistics
// ---------------------------------------------------------------------------
__global__ void zero_stats()
{
    int t = threadIdx.x;   // 512 threads
    g_sum[t] = 0.0;
    g_sumsq[t] = 0.0;
}

__global__ __launch_bounds__(256) void bn_stats()
{
    const int tid = threadIdx.x;
    const int row0 = blockIdx.x * 128;
    const int c1 = tid, c2 = tid + 256;
    float s1 = 0.f, q1 = 0.f, s2 = 0.f, q2 = 0.f;
    for (int r = 0; r < 128; r++) {
        const float* p = g_y2 + (size_t)(row0 + r) * C_;
        float v1 = p[c1], v2 = p[c2];
        s1 += v1; q1 += v1 * v1;
        s2 += v2; q2 += v2 * v2;
    }
    atomicAdd(&g_sum[c1],   (double)s1);
    atomicAdd(&g_sumsq[c1], (double)q1);
    atomicAdd(&g_sum[c2],   (double)s2);
    atomicAdd(&g_sumsq[c2], (double)q2);
}

// ---------------------------------------------------------------------------
// BN normalize + residual + [B,N,C]->[B,C,N] transpose
// ---------------------------------------------------------------------------
__global__ __launch_bounds__(256) void bn_final(
    const float* __restrict__ x,
    const float* __restrict__ bn_w, const float* __restrict__ bn_b,
    float* __restrict__ out)
{
    __shared__ float t[32][33];
    const int b  = blockIdx.z;
    const int c0 = blockIdx.y * 32;
    const int n0 = blockIdx.x * 32;
    const int tx = threadIdx.x, ty = threadIdx.y;

    #pragma unroll
    for (int j = 0; j < 32; j += 8) {
        int n = n0 + ty + j;
        t[ty + j][tx] = g_y2[((size_t)(b * N_ + n)) * C_ + c0 + tx];
    }
    __syncthreads();

    const double cnt = (double)ROWS_TOTAL;
    #pragma unroll
    for (int j = 0; j < 32; j += 8) {
        int c = c0 + ty + j;
        double mean = g_sum[c] / cnt;
        double var  = g_sumsq[c] / cnt - mean * mean;
        float inv = (float)rsqrt(var + 1e-5);
        float w = bn_w[c], bb = bn_b[c];
        int n = n0 + tx;
        size_t oidx = ((size_t)b * C_ + c) * (size_t)N_ + n;
        float v = t[tx][ty + j];
        out[oidx] = (v - (float)mean) * inv * w + bb + x[oidx];
    }
}

// ---------------------------------------------------------------------------
// Launch
// ---------------------------------------------------------------------------
extern "C" void kernel_launch(void* const* d_in, const int* in_sizes, int n_in,
                              void* d_out, int out_size)
{
    const float* x       = (const float*)d_in[0];
    const float* theta_w = (const float*)d_in[1];
    const float* theta_b = (const float*)d_in[2];
    const float* phi_w   = (const float*)d_in[3];
    const float* phi_b   = (const float*)d_in[4];
    const float* gw      = (const float*)d_in[5];
    const float* gb      = (const float*)d_in[6];
    const float* wz_w    = (const float*)d_in[7];
    const float* wz_b    = (const float*)d_in[8];
    const float* bn_w    = (const float*)d_in[9];
    const float* bn_b    = (const float*)d_in[10];
    float* out = (float*)d_out;

    float *Q, *K, *V, *S, *y1, *y2;
    cudaGetSymbolAddress((void**)&Q,  g_Q);
    cudaGetSymbolAddress((void**)&K,  g_K);
    cudaGetSymbolAddress((void**)&V,  g_V);
    cudaGetSymbolAddress((void**)&S,  g_S);
    cudaGetSymbolAddress((void**)&y1, g_y1);
    cudaGetSymbolAddress((void**)&y2, g_y2);

    zero_stats<<<1, 512>>>();

    // --- QKV projections (64x64): C[n,i] = sum_c x[c*N+n]*W[i*C+c] + b[i]
    {
        dim3 g(N_ / BM, IC_ / BN, B_);
        long long bA = (long long)C_ * N_, bC = (long long)NP_ * IC_;
        gemm_tc<false, true, true><<<g, 128>>>(x, theta_w, theta_b, Q,
            C_, N_, C_, IC_, bA, 0, bC);
        gemm_tc<false, true, true><<<g, 128>>>(x, phi_w, phi_b, K,
            C_, N_, C_, IC_, bA, 0, bC);
        gemm_tc<false, true, true><<<g, 128>>>(x, gw, gb, V,
            C_, N_, C_, IC_, bA, 0, bC);
    }

    // --- S = Q * K^T (128x128 double-buffered), padded m,n = 3200
    {
        dim3 g(NP_ / BM2, NP_ / BN2, B_);
        gemm_tc128<true, false><<<g, 256>>>(Q, K, nullptr, S,
            IC_, IC_, IC_, NP_,
            (long long)NP_ * IC_, (long long)NP_ * IC_, (long long)NP_ * NP_);
    }

    // --- softmax over valid rows/cols of padded S
    softmax_rows<<<dim3(N_, B_), 256>>>(S);

    // --- y1 = P * V (128x128 double-buffered); K runs only over valid 3136
    {
        dim3 g(NP_ / BM2, IC_ / BN2, B_);
        gemm_tc128<false, false><<<g, 256>>>(S, V, nullptr, y1,
            N_, NP_, IC_, IC_,
            (long long)NP_ * NP_, (long long)NP_ * IC_, (long long)NP_ * IC_);
    }

    // --- y2 = y1 * Wz^T + b (64x64), valid rows only
    {
        dim3 g(N_ / BM, C_ / BN, B_);
        gemm_tc<true, true, true><<<g, 128>>>(y1, wz_w, wz_b, y2,
            IC_, IC_, IC_, C_,
            (long long)NP_ * IC_, 0, (long long)N_ * C_);
    }

    // --- BN stats + normalize + residual + transpose
    bn_stats<<<196, 256>>>();
    bn_final<<<dim3(N_ / 32, C_ / 32, B_), dim3(32, 8)>>>(x, bn_w, bn_b, out);
}

// round 5
// speedup vs baseline: 2.3954x; 1.3184x over previous
#include <cuda_runtime.h>
#include <cuda_fp16.h>
#include <math.h>
#include <stdint.h>

// Problem constants
#define B_   8
#define C_   512
#define N_   3136   // 56*56
#define NP_  3200   // N padded to multiple of 128
#define IC_  256
#define ROWS_TOTAL (B_ * N_)   // 25088

// ---------------------------------------------------------------------------
// Scratch
// ---------------------------------------------------------------------------
__device__ float  g_Q [(size_t)B_ * NP_ * IC_];
__device__ float  g_K [(size_t)B_ * NP_ * IC_];
__device__ __half g_Vt[(size_t)B_ * IC_ * NP_];   // V transposed: [b][i][token]
__device__ float  g_S [(size_t)B_ * NP_ * NP_];   // logits fp32
__device__ __half g_P [(size_t)B_ * NP_ * NP_];   // softmax probs fp16
__device__ float  g_y1[(size_t)B_ * NP_ * IC_];
__device__ float  g_y2[(size_t)B_ * N_ * C_];
__device__ double g_sum[C_];
__device__ double g_sumsq[C_];

// ---------------------------------------------------------------------------
// mma helpers
// ---------------------------------------------------------------------------
__device__ __forceinline__ uint32_t f2tf32(float x) {
    uint32_t u;
    asm("cvt.rna.tf32.f32 %0, %1;" : "=r"(u) : "f"(x));
    return u;
}
__device__ __forceinline__ uint4 cvt4(float4 v) {
    return make_uint4(f2tf32(v.x), f2tf32(v.y), f2tf32(v.z), f2tf32(v.w));
}
__device__ __forceinline__ void mma_tf32(float& d0, float& d1, float& d2, float& d3,
                                         uint32_t a0, uint32_t a1, uint32_t a2, uint32_t a3,
                                         uint32_t b0, uint32_t b1) {
    asm volatile(
        "mma.sync.aligned.m16n8k8.row.col.f32.tf32.tf32.f32 "
        "{%0,%1,%2,%3}, {%4,%5,%6,%7}, {%8,%9}, {%0,%1,%2,%3};\n"
        : "+f"(d0), "+f"(d1), "+f"(d2), "+f"(d3)
        : "r"(a0), "r"(a1), "r"(a2), "r"(a3), "r"(b0), "r"(b1));
}
__device__ __forceinline__ void mma_f16(float& d0, float& d1, float& d2, float& d3,
                                        uint32_t a0, uint32_t a1, uint32_t a2, uint32_t a3,
                                        uint32_t b0, uint32_t b1) {
    asm volatile(
        "mma.sync.aligned.m16n8k16.row.col.f32.f16.f16.f32 "
        "{%0,%1,%2,%3}, {%4,%5,%6,%7}, {%8,%9}, {%0,%1,%2,%3};\n"
        : "+f"(d0), "+f"(d1), "+f"(d2), "+f"(d3)
        : "r"(a0), "r"(a1), "r"(a2), "r"(a3), "r"(b0), "r"(b1));
}

// ===========================================================================
// Fused QKV projection: one x-tile feeds theta/phi/g weight tiles.
// 64x64x16 tiles, 128 threads (2x2 warps), warp tile 32x32.
// Writes Q, K as fp32 row-major [token][i]; V as fp16 TRANSPOSED [i][token].
// ===========================================================================
constexpr int BM = 64, BN = 64, BK = 16;
constexpr int S_RK = BK + 4;   // 20
constexpr int S_KM = BM + 8;   // 72

__global__ __launch_bounds__(128) void qkv_fused(
    const float* __restrict__ x,
    const float* __restrict__ tw, const float* __restrict__ tb,
    const float* __restrict__ pw, const float* __restrict__ pb,
    const float* __restrict__ gw, const float* __restrict__ gb,
    float* __restrict__ Q, float* __restrict__ K, __half* __restrict__ Vt)
{
    const long long z = blockIdx.z;
    x  += z * (long long)C_ * N_;
    Q  += z * (long long)NP_ * IC_;
    K  += z * (long long)NP_ * IC_;
    Vt += z * (long long)IC_ * NP_;

    const int m0 = blockIdx.x * BM;   // tokens
    const int n0 = blockIdx.y * BN;   // inter-channels
    const int tid = threadIdx.x;
    const int w = tid >> 5, lane = tid & 31;
    const int gid = lane >> 2, tig = lane & 3;
    const int wm = (w & 1) * 32, wn = (w >> 1) * 32;

    __shared__ uint32_t As[BK * S_KM];
    __shared__ uint32_t Bs[3][BN * S_RK];

    const float* Ws[3] = {tw, pw, gw};

    float acc[3][2][4][4];
    #pragma unroll
    for (int s = 0; s < 3; s++)
        #pragma unroll
        for (int i = 0; i < 2; i++)
            #pragma unroll
            for (int j = 0; j < 4; j++)
                #pragma unroll
                for (int r = 0; r < 4; r++) acc[s][i][j][r] = 0.0f;

    for (int c0 = 0; c0 < C_; c0 += BK) {
        // x tile: [k=c][m=token], m contiguous
        #pragma unroll
        for (int it = 0; it < 2; it++) {
            int lin = tid + it * 128;
            int kk = lin >> 4, m4 = (lin & 15) << 2;
            float4 v = *(const float4*)(x + (long long)(c0 + kk) * N_ + m0 + m4);
            *(uint4*)(&As[kk * S_KM + m4]) = cvt4(v);
        }
        // 3 weight tiles: [n=i][k=c], k contiguous
        #pragma unroll
        for (int s = 0; s < 3; s++) {
            #pragma unroll
            for (int it = 0; it < 2; it++) {
                int lin = tid + it * 128;
                int nn = lin >> 2, k4 = (lin & 3) << 2;
                float4 v = *(const float4*)(Ws[s] + (long long)(n0 + nn) * C_ + c0 + k4);
                *(uint4*)(&Bs[s][nn * S_RK + k4]) = cvt4(v);
            }
        }
        __syncthreads();

        #pragma unroll
        for (int ks = 0; ks < 2; ks++) {
            const int kk = ks * 8;
            uint32_t af[2][4];
            #pragma unroll
            for (int i = 0; i < 2; i++) {
                int row = wm + i * 16;
                af[i][0] = As[(kk + tig)     * S_KM + row + gid];
                af[i][1] = As[(kk + tig)     * S_KM + row + gid + 8];
                af[i][2] = As[(kk + tig + 4) * S_KM + row + gid];
                af[i][3] = As[(kk + tig + 4) * S_KM + row + gid + 8];
            }
            #pragma unroll
            for (int s = 0; s < 3; s++) {
                uint32_t bf[4][2];
                #pragma unroll
                for (int j = 0; j < 4; j++) {
                    int col = wn + j * 8;
                    bf[j][0] = Bs[s][(col + gid) * S_RK + kk + tig];
                    bf[j][1] = Bs[s][(col + gid) * S_RK + kk + tig + 4];
                }
                #pragma unroll
                for (int i = 0; i < 2; i++)
                    #pragma unroll
                    for (int j = 0; j < 4; j++)
                        mma_tf32(acc[s][i][j][0], acc[s][i][j][1], acc[s][i][j][2], acc[s][i][j][3],
                                 af[i][0], af[i][1], af[i][2], af[i][3],
                                 bf[j][0], bf[j][1]);
            }
        }
        __syncthreads();
    }

    // epilogues
    #pragma unroll
    for (int i = 0; i < 2; i++) {
        int grow = m0 + wm + i * 16 + gid;
        #pragma unroll
        for (int j = 0; j < 4; j++) {
            int gcol = n0 + wn + j * 8 + tig * 2;
            // Q
            {
                float b0v = tb[gcol], b1v = tb[gcol + 1];
                *(float2*)(Q + (long long)grow * IC_ + gcol) =
                    make_float2(acc[0][i][j][0] + b0v, acc[0][i][j][1] + b1v);
                *(float2*)(Q + (long long)(grow + 8) * IC_ + gcol) =
                    make_float2(acc[0][i][j][2] + b0v, acc[0][i][j][3] + b1v);
            }
            // K
            {
                float b0v = pb[gcol], b1v = pb[gcol + 1];
                *(float2*)(K + (long long)grow * IC_ + gcol) =
                    make_float2(acc[1][i][j][0] + b0v, acc[1][i][j][1] + b1v);
                *(float2*)(K + (long long)(grow + 8) * IC_ + gcol) =
                    make_float2(acc[1][i][j][2] + b0v, acc[1][i][j][3] + b1v);
            }
            // V transposed, fp16
            {
                float b0v = gb[gcol], b1v = gb[gcol + 1];
                Vt[(long long)gcol       * NP_ + grow]     = __float2half_rn(acc[2][i][j][0] + b0v);
                Vt[(long long)(gcol + 1) * NP_ + grow]     = __float2half_rn(acc[2][i][j][1] + b1v);
                Vt[(long long)gcol       * NP_ + grow + 8] = __float2half_rn(acc[2][i][j][2] + b0v);
                Vt[(long long)(gcol + 1) * NP_ + grow + 8] = __float2half_rn(acc[2][i][j][3] + b1v);
            }
        }
    }
}

// ===========================================================================
// 64x64x16 tf32 GEMM (y2 only): A k-contig, B k-contig, bias.
// ===========================================================================
__global__ __launch_bounds__(128) void gemm_y2(
    const float* __restrict__ A, const float* __restrict__ Bm,
    const float* __restrict__ bias, float* __restrict__ Cc,
    int K, int sA, int sB, int ldc, long long batA, long long batC)
{
    A  += (long long)blockIdx.z * batA;
    Cc += (long long)blockIdx.z * batC;

    const int m0 = blockIdx.x * BM;
    const int n0 = blockIdx.y * BN;
    const int tid = threadIdx.x;
    const int w = tid >> 5, lane = tid & 31;
    const int gid = lane >> 2, tig = lane & 3;
    const int wm = (w & 1) * 32, wn = (w >> 1) * 32;

    __shared__ uint32_t As[BM * S_RK];
    __shared__ uint32_t Bs[BN * S_RK];

    float acc[2][4][4];
    #pragma unroll
    for (int i = 0; i < 2; i++)
        #pragma unroll
        for (int j = 0; j < 4; j++)
            #pragma unroll
            for (int r = 0; r < 4; r++) acc[i][j][r] = 0.0f;

    for (int k0 = 0; k0 < K; k0 += BK) {
        #pragma unroll
        for (int it = 0; it < 2; it++) {
            int lin = tid + it * 128;
            int mm = lin >> 2, k4 = (lin & 3) << 2;
            float4 v = *(const float4*)(A + (long long)(m0 + mm) * sA + k0 + k4);
            *(uint4*)(&As[mm * S_RK + k4]) = cvt4(v);
        }
        #pragma unroll
        for (int it = 0; it < 2; it++) {
            int lin = tid + it * 128;
            int nn = lin >> 2, k4 = (lin & 3) << 2;
            float4 v = *(const float4*)(Bm + (long long)(n0 + nn) * sB + k0 + k4);
            *(uint4*)(&Bs[nn * S_RK + k4]) = cvt4(v);
        }
        __syncthreads();

        #pragma unroll
        for (int ks = 0; ks < 2; ks++) {
            const int kk = ks * 8;
            uint32_t af[2][4];
            #pragma unroll
            for (int i = 0; i < 2; i++) {
                int row = wm + i * 16;
                af[i][0] = As[(row + gid)     * S_RK + kk + tig];
                af[i][1] = As[(row + gid + 8) * S_RK + kk + tig];
                af[i][2] = As[(row + gid)     * S_RK + kk + tig + 4];
                af[i][3] = As[(row + gid + 8) * S_RK + kk + tig + 4];
            }
            uint32_t bf[4][2];
            #pragma unroll
            for (int j = 0; j < 4; j++) {
                int col = wn + j * 8;
                bf[j][0] = Bs[(col + gid) * S_RK + kk + tig];
                bf[j][1] = Bs[(col + gid) * S_RK + kk + tig + 4];
            }
            #pragma unroll
            for (int i = 0; i < 2; i++)
                #pragma unroll
                for (int j = 0; j < 4; j++)
                    mma_tf32(acc[i][j][0], acc[i][j][1], acc[i][j][2], acc[i][j][3],
                             af[i][0], af[i][1], af[i][2], af[i][3],
                             bf[j][0], bf[j][1]);
        }
        __syncthreads();
    }

    #pragma unroll
    for (int i = 0; i < 2; i++) {
        int grow = m0 + wm + i * 16 + gid;
        #pragma unroll
        for (int j = 0; j < 4; j++) {
            int gcol = n0 + wn + j * 8 + tig * 2;
            float b0v = bias[gcol], b1v = bias[gcol + 1];
            *(float2*)(Cc + (long long)grow * ldc + gcol) =
                make_float2(acc[i][j][0] + b0v, acc[i][j][1] + b1v);
            *(float2*)(Cc + (long long)(grow + 8) * ldc + gcol) =
                make_float2(acc[i][j][2] + b0v, acc[i][j][3] + b1v);
        }
    }
}

// ===========================================================================
// S = Q*K^T : 128x128x16 double-buffered tf32 (both A,B k-contiguous)
// ===========================================================================
constexpr int BM2 = 128, BN2 = 128, BK2 = 16;
constexpr int SRK2 = BK2 + 4;    // 20
constexpr int SBUF = BM2 * SRK2;

__global__ __launch_bounds__(256) void gemm_s(
    const float* __restrict__ A, const float* __restrict__ Bm,
    float* __restrict__ Cc)
{
    const long long z = blockIdx.z;
    A  += z * (long long)NP_ * IC_;
    Bm += z * (long long)NP_ * IC_;
    Cc += z * (long long)NP_ * NP_;

    const int m0 = blockIdx.x * BM2;
    const int n0 = blockIdx.y * BN2;
    const int tid = threadIdx.x;
    const int w = tid >> 5, lane = tid & 31;
    const int gid = lane >> 2, tig = lane & 3;
    const int wm = (w & 1) * 64, wn = (w >> 1) * 32;

    __shared__ uint32_t As[2][SBUF];
    __shared__ uint32_t Bs[2][SBUF];

    float acc[4][4][4];
    #pragma unroll
    for (int i = 0; i < 4; i++)
        #pragma unroll
        for (int j = 0; j < 4; j++)
            #pragma unroll
            for (int r = 0; r < 4; r++) acc[i][j][r] = 0.0f;

    float4 ra[2], rb[2];
    auto gload = [&](int k0) {
        #pragma unroll
        for (int it = 0; it < 2; it++) {
            int lin = tid + it * 256;
            int mm = lin >> 2, k4 = (lin & 3) << 2;
            ra[it] = *(const float4*)(A + (long long)(m0 + mm) * IC_ + k0 + k4);
            rb[it] = *(const float4*)(Bm + (long long)(n0 + mm) * IC_ + k0 + k4);
        }
    };
    auto sstore = [&](int b) {
        #pragma unroll
        for (int it = 0; it < 2; it++) {
            int lin = tid + it * 256;
            int mm = lin >> 2, k4 = (lin & 3) << 2;
            *(uint4*)(&As[b][mm * SRK2 + k4]) = cvt4(ra[it]);
            *(uint4*)(&Bs[b][mm * SRK2 + k4]) = cvt4(rb[it]);
        }
    };

    gload(0); sstore(0); __syncthreads();
    int buf = 0;
    for (int k0 = 0; k0 < IC_; k0 += BK2) {
        const bool nxt = (k0 + BK2 < IC_);
        if (nxt) gload(k0 + BK2);

        const uint32_t* Ab = As[buf];
        const uint32_t* Bb = Bs[buf];
        #pragma unroll
        for (int ks = 0; ks < 2; ks++) {
            const int kk = ks * 8;
            uint32_t af[4][4];
            #pragma unroll
            for (int i = 0; i < 4; i++) {
                int row = wm + i * 16;
                af[i][0] = Ab[(row + gid)     * SRK2 + kk + tig];
                af[i][1] = Ab[(row + gid + 8) * SRK2 + kk + tig];
                af[i][2] = Ab[(row + gid)     * SRK2 + kk + tig + 4];
                af[i][3] = Ab[(row + gid + 8) * SRK2 + kk + tig + 4];
            }
            uint32_t bf[4][2];
            #pragma unroll
            for (int j = 0; j < 4; j++) {
                int col = wn + j * 8;
                bf[j][0] = Bb[(col + gid) * SRK2 + kk + tig];
                bf[j][1] = Bb[(col + gid) * SRK2 + kk + tig + 4];
            }
            #pragma unroll
            for (int i = 0; i < 4; i++)
                #pragma unroll
                for (int j = 0; j < 4; j++)
                    mma_tf32(acc[i][j][0], acc[i][j][1], acc[i][j][2], acc[i][j][3],
                             af[i][0], af[i][1], af[i][2], af[i][3],
                             bf[j][0], bf[j][1]);
        }
        if (nxt) { sstore(buf ^ 1); __syncthreads(); buf ^= 1; }
    }

    #pragma unroll
    for (int i = 0; i < 4; i++) {
        int grow = m0 + wm + i * 16 + gid;
        #pragma unroll
        for (int j = 0; j < 4; j++) {
            int gcol = n0 + wn + j * 8 + tig * 2;
            *(float2*)(Cc + (long long)grow * NP_ + gcol) =
                make_float2(acc[i][j][0], acc[i][j][1]);
            *(float2*)(Cc + (long long)(grow + 8) * NP_ + gcol) =
                make_float2(acc[i][j][2], acc[i][j][3]);
        }
    }
}

// ===========================================================================
// y1 = P*V : fp16 mma m16n8k16, 128x128x32 double-buffered.
// P [q][k] fp16 k-contig; Vt [i][k] fp16 k-contig (pre-transposed).
// ===========================================================================
constexpr int PVK = 32;        // k halves per iter
constexpr int PSTRW = 20;      // 40 halves = 20 words per row

__global__ __launch_bounds__(256) void pv_fp16(
    const __half* __restrict__ P, const __half* __restrict__ Vt,
    float* __restrict__ Y)
{
    const long long z = blockIdx.z;
    P  += z * (long long)NP_ * NP_;
    Vt += z * (long long)IC_ * NP_;
    Y  += z * (long long)NP_ * IC_;

    const int m0 = blockIdx.x * 128;   // q rows
    const int n0 = blockIdx.y * 128;   // i cols
    const int tid = threadIdx.x;
    const int w = tid >> 5, lane = tid & 31;
    const int gid = lane >> 2, tig = lane & 3;
    const int wm = (w & 1) * 64, wn = (w >> 1) * 32;

    __shared__ uint32_t Ps[2][128 * PSTRW];
    __shared__ uint32_t Vs[2][128 * PSTRW];

    float acc[4][4][4];
    #pragma unroll
    for (int i = 0; i < 4; i++)
        #pragma unroll
        for (int j = 0; j < 4; j++)
            #pragma unroll
            for (int r = 0; r < 4; r++) acc[i][j][r] = 0.0f;

    uint4 rp[2], rv[2];
    auto gload = [&](int k0) {
        #pragma unroll
        for (int it = 0; it < 2; it++) {
            int lin = tid + it * 256;
            int row = lin >> 2, k8 = (lin & 3) << 3;
            rp[it] = *(const uint4*)(P  + (long long)(m0 + row) * NP_ + k0 + k8);
            rv[it] = *(const uint4*)(Vt + (long long)(n0 + row) * NP_ + k0 + k8);
        }
    };
    auto sstore = [&](int b) {
        #pragma unroll
        for (int it = 0; it < 2; it++) {
            int lin = tid + it * 256;
            int row = lin >> 2, kw = (lin & 3) << 2;   // word offset 0,4,8,12
            *(uint4*)(&Ps[b][row * PSTRW + kw]) = rp[it];
            *(uint4*)(&Vs[b][row * PSTRW + kw]) = rv[it];
        }
    };

    gload(0); sstore(0); __syncthreads();
    int buf = 0;
    for (int k0 = 0; k0 < N_; k0 += PVK) {
        const bool nxt = (k0 + PVK < N_);
        if (nxt) gload(k0 + PVK);

        const uint32_t* Pb = Ps[buf];
        const uint32_t* Vb = Vs[buf];
        #pragma unroll
        for (int ks = 0; ks < 2; ks++) {
            const int kc = ks * 8;   // word offset (16 halves per k-step)
            uint32_t af[4][4];
            #pragma unroll
            for (int i = 0; i < 4; i++) {
                int row = wm + i * 16;
                af[i][0] = Pb[(row + gid)     * PSTRW + kc + tig];
                af[i][1] = Pb[(row + gid + 8) * PSTRW + kc + tig];
                af[i][2] = Pb[(row + gid)     * PSTRW + kc + tig + 4];
                af[i][3] = Pb[(row + gid + 8) * PSTRW + kc + tig + 4];
            }
            uint32_t bf[4][2];
            #pragma unroll
            for (int j = 0; j < 4; j++) {
                int col = wn + j * 8;
                bf[j][0] = Vb[(col + gid) * PSTRW + kc + tig];
                bf[j][1] = Vb[(col + gid) * PSTRW + kc + tig + 4];
            }
            #pragma unroll
            for (int i = 0; i < 4; i++)
                #pragma unroll
                for (int j = 0; j < 4; j++)
                    mma_f16(acc[i][j][0], acc[i][j][1], acc[i][j][2], acc[i][j][3],
                            af[i][0], af[i][1], af[i][2], af[i][3],
                            bf[j][0], bf[j][1]);
        }
        if (nxt) { sstore(buf ^ 1); __syncthreads(); buf ^= 1; }
    }

    #pragma unroll
    for (int i = 0; i < 4; i++) {
        int grow = m0 + wm + i * 16 + gid;
        #pragma unroll
        for (int j = 0; j < 4; j++) {
            int gcol = n0 + wn + j * 8 + tig * 2;
            *(float2*)(Y + (long long)grow * IC_ + gcol) =
                make_float2(acc[i][j][0], acc[i][j][1]);
            *(float2*)(Y + (long long)(grow + 8) * IC_ + gcol) =
                make_float2(acc[i][j][2], acc[i][j][3]);
        }
    }
}

// ---------------------------------------------------------------------------
// Row softmax: read fp32 logits, write fp16 probs. grid (N_, B_).
// ---------------------------------------------------------------------------
__global__ __launch_bounds__(256) void softmax_rows(
    const float* __restrict__ S, __half* __restrict__ P)
{
    __shared__ float buf[N_];
    __shared__ float red[256];
    const float* row = S + (size_t)blockIdx.y * NP_ * NP_ + (size_t)blockIdx.x * NP_;
    __half* prow     = P + (size_t)blockIdx.y * NP_ * NP_ + (size_t)blockIdx.x * NP_;
    const int tid = threadIdx.x;

    float m = -1e30f;
    for (int i = tid; i < N_; i += 256) {
        float v = row[i];
        buf[i] = v;
        m = fmaxf(m, v);
    }
    red[tid] = m;
    __syncthreads();
    for (int s = 128; s > 0; s >>= 1) {
        if (tid < s) red[tid] = fmaxf(red[tid], red[tid + s]);
        __syncthreads();
    }
    m = red[0];
    __syncthreads();

    float sum = 0.f;
    for (int i = tid; i < N_; i += 256) {
        float e = expf(buf[i] - m);
        buf[i] = e;
        sum += e;
    }
    red[tid] = sum;
    __syncthreads();
    for (int s = 128; s > 0; s >>= 1) {
        if (tid < s) red[tid] += red[tid + s];
        __syncthreads();
    }
    float inv = 1.0f / red[0];
    // vectorized half2 writes (N_ even)
    for (int i = tid * 2; i < N_; i += 512) {
        __half2 h = __floats2half2_rn(buf[i] * inv, buf[i + 1] * inv);
        *(__half2*)(prow + i) = h;
    }
}

// ---------------------------------------------------------------------------
// BN statistics + final
// ---------------------------------------------------------------------------
__global__ void zero_stats()
{
    int t = threadIdx.x;   // 512 threads
    g_sum[t] = 0.0;
    g_sumsq[t] = 0.0;
}

__global__ __launch_bounds__(256) void bn_stats()
{
    const int tid = threadIdx.x;
    const int row0 = blockIdx.x * 128;
    const int c1 = tid, c2 = tid + 256;
    float s1 = 0.f, q1 = 0.f, s2 = 0.f, q2 = 0.f;
    for (int r = 0; r < 128; r++) {
        const float* p = g_y2 + (size_t)(row0 + r) * C_;
        float v1 = p[c1], v2 = p[c2];
        s1 += v1; q1 += v1 * v1;
        s2 += v2; q2 += v2 * v2;
    }
    atomicAdd(&g_sum[c1],   (double)s1);
    atomicAdd(&g_sumsq[c1], (double)q1);
    atomicAdd(&g_sum[c2],   (double)s2);
    atomicAdd(&g_sumsq[c2], (double)q2);
}

__global__ __launch_bounds__(256) void bn_final(
    const float* __restrict__ x,
    const float* __restrict__ bn_w, const float* __restrict__ bn_b,
    float* __restrict__ out)
{
    __shared__ float t[32][33];
    const int b  = blockIdx.z;
    const int c0 = blockIdx.y * 32;
    const int n0 = blockIdx.x * 32;
    const int tx = threadIdx.x, ty = threadIdx.y;

    #pragma unroll
    for (int j = 0; j < 32; j += 8) {
        int n = n0 + ty + j;
        t[ty + j][tx] = g_y2[((size_t)(b * N_ + n)) * C_ + c0 + tx];
    }
    __syncthreads();

    const double cnt = (double)ROWS_TOTAL;
    #pragma unroll
    for (int j = 0; j < 32; j += 8) {
        int c = c0 + ty + j;
        double mean = g_sum[c] / cnt;
        double var  = g_sumsq[c] / cnt - mean * mean;
        float inv = (float)rsqrt(var + 1e-5);
        float w = bn_w[c], bb = bn_b[c];
        int n = n0 + tx;
        size_t oidx = ((size_t)b * C_ + c) * (size_t)N_ + n;
        float v = t[tx][ty + j];
        out[oidx] = (v - (float)mean) * inv * w + bb + x[oidx];
    }
}

// ---------------------------------------------------------------------------
// Launch
// ---------------------------------------------------------------------------
extern "C" void kernel_launch(void* const* d_in, const int* in_sizes, int n_in,
                              void* d_out, int out_size)
{
    const float* x       = (const float*)d_in[0];
    const float* theta_w = (const float*)d_in[1];
    const float* theta_b = (const float*)d_in[2];
    const float* phi_w   = (const float*)d_in[3];
    const float* phi_b   = (const float*)d_in[4];
    const float* gw      = (const float*)d_in[5];
    const float* gb      = (const float*)d_in[6];
    const float* wz_w    = (const float*)d_in[7];
    const float* wz_b    = (const float*)d_in[8];
    const float* bn_w    = (const float*)d_in[9];
    const float* bn_b    = (const float*)d_in[10];
    float* out = (float*)d_out;

    float *Q, *K, *S, *y1, *y2;
    __half *Vt, *P;
    cudaGetSymbolAddress((void**)&Q,  g_Q);
    cudaGetSymbolAddress((void**)&K,  g_K);
    cudaGetSymbolAddress((void**)&Vt, g_Vt);
    cudaGetSymbolAddress((void**)&S,  g_S);
    cudaGetSymbolAddress((void**)&P,  g_P);
    cudaGetSymbolAddress((void**)&y1, g_y1);
    cudaGetSymbolAddress((void**)&y2, g_y2);

    zero_stats<<<1, 512>>>();

    // fused QKV projections
    qkv_fused<<<dim3(N_ / BM, IC_ / BN, B_), 128>>>(
        x, theta_w, theta_b, phi_w, phi_b, gw, gb, Q, K, Vt);

    // S = Q K^T (tf32, 128x128 double-buffered)
    gemm_s<<<dim3(NP_ / BM2, NP_ / BN2, B_), 256>>>(Q, K, S);

    // softmax rows -> fp16 probs
    softmax_rows<<<dim3(N_, B_), 256>>>(S, P);

    // y1 = P V (fp16 mma)
    pv_fp16<<<dim3(NP_ / 128, IC_ / 128, B_), 256>>>(P, Vt, y1);

    // y2 = y1 Wz^T + b (tf32)
    gemm_y2<<<dim3(N_ / BM, C_ / BN, B_), 128>>>(y1, wz_w, wz_b, y2,
        IC_, IC_, IC_, C_, (long long)NP_ * IC_, (long long)N_ * C_);

    // BN stats + normalize + residual + transpose
    bn_stats<<<196, 256>>>();
    bn_final<<<dim3(N_ / 32, C_ / 32, B_), dim3(32, 8)>>>(x, bn_w, bn_b, out);
}

// round 6
// speedup vs baseline: 2.5706x; 1.0731x over previous
#include <cuda_runtime.h>
#include <cuda_fp16.h>
#include <math.h>
#include <stdint.h>

// Problem constants
#define B_   8
#define C_   512
#define N_   3136   // 56*56
#define NP_  3200   // N padded to multiple of 128
#define IC_  256
#define ROWS_TOTAL (B_ * N_)   // 25088

// ---------------------------------------------------------------------------
// Scratch
// ---------------------------------------------------------------------------
__device__ float  g_Q [(size_t)B_ * NP_ * IC_];
__device__ float  g_K [(size_t)B_ * NP_ * IC_];
__device__ __half g_Vt[(size_t)B_ * IC_ * NP_];   // V transposed: [b][i][token]
__device__ float  g_S [(size_t)B_ * NP_ * NP_];   // logits fp32
__device__ __half g_P [(size_t)B_ * NP_ * NP_];   // softmax probs fp16
__device__ float  g_y1[(size_t)B_ * NP_ * IC_];
__device__ float  g_y2[(size_t)B_ * N_ * C_];
__device__ double g_sum[C_];
__device__ double g_sumsq[C_];

// ---------------------------------------------------------------------------
// mma helpers
// ---------------------------------------------------------------------------
__device__ __forceinline__ uint32_t f2tf32(float x) {
    uint32_t u;
    asm("cvt.rna.tf32.f32 %0, %1;" : "=r"(u) : "f"(x));
    return u;
}
__device__ __forceinline__ uint4 cvt4(float4 v) {
    return make_uint4(f2tf32(v.x), f2tf32(v.y), f2tf32(v.z), f2tf32(v.w));
}
__device__ __forceinline__ void mma_tf32(float& d0, float& d1, float& d2, float& d3,
                                         uint32_t a0, uint32_t a1, uint32_t a2, uint32_t a3,
                                         uint32_t b0, uint32_t b1) {
    asm volatile(
        "mma.sync.aligned.m16n8k8.row.col.f32.tf32.tf32.f32 "
        "{%0,%1,%2,%3}, {%4,%5,%6,%7}, {%8,%9}, {%0,%1,%2,%3};\n"
        : "+f"(d0), "+f"(d1), "+f"(d2), "+f"(d3)
        : "r"(a0), "r"(a1), "r"(a2), "r"(a3), "r"(b0), "r"(b1));
}
__device__ __forceinline__ void mma_f16(float& d0, float& d1, float& d2, float& d3,
                                        uint32_t a0, uint32_t a1, uint32_t a2, uint32_t a3,
                                        uint32_t b0, uint32_t b1) {
    asm volatile(
        "mma.sync.aligned.m16n8k16.row.col.f32.f16.f16.f32 "
        "{%0,%1,%2,%3}, {%4,%5,%6,%7}, {%8,%9}, {%0,%1,%2,%3};\n"
        : "+f"(d0), "+f"(d1), "+f"(d2), "+f"(d3)
        : "r"(a0), "r"(a1), "r"(a2), "r"(a3), "r"(b0), "r"(b1));
}

// ===========================================================================
// Fused QKV projection (unchanged from R4)
// ===========================================================================
constexpr int BM = 64, BN = 64, BK = 16;
constexpr int S_RK = BK + 4;   // 20
constexpr int S_KM = BM + 8;   // 72

__global__ __launch_bounds__(128) void qkv_fused(
    const float* __restrict__ x,
    const float* __restrict__ tw, const float* __restrict__ tb,
    const float* __restrict__ pw, const float* __restrict__ pb,
    const float* __restrict__ gw, const float* __restrict__ gb,
    float* __restrict__ Q, float* __restrict__ K, __half* __restrict__ Vt)
{
    const long long z = blockIdx.z;
    x  += z * (long long)C_ * N_;
    Q  += z * (long long)NP_ * IC_;
    K  += z * (long long)NP_ * IC_;
    Vt += z * (long long)IC_ * NP_;

    const int m0 = blockIdx.x * BM;
    const int n0 = blockIdx.y * BN;
    const int tid = threadIdx.x;
    const int w = tid >> 5, lane = tid & 31;
    const int gid = lane >> 2, tig = lane & 3;
    const int wm = (w & 1) * 32, wn = (w >> 1) * 32;

    __shared__ uint32_t As[BK * S_KM];
    __shared__ uint32_t Bs[3][BN * S_RK];

    const float* Ws[3] = {tw, pw, gw};

    float acc[3][2][4][4];
    #pragma unroll
    for (int s = 0; s < 3; s++)
        #pragma unroll
        for (int i = 0; i < 2; i++)
            #pragma unroll
            for (int j = 0; j < 4; j++)
                #pragma unroll
                for (int r = 0; r < 4; r++) acc[s][i][j][r] = 0.0f;

    for (int c0 = 0; c0 < C_; c0 += BK) {
        #pragma unroll
        for (int it = 0; it < 2; it++) {
            int lin = tid + it * 128;
            int kk = lin >> 4, m4 = (lin & 15) << 2;
            float4 v = *(const float4*)(x + (long long)(c0 + kk) * N_ + m0 + m4);
            *(uint4*)(&As[kk * S_KM + m4]) = cvt4(v);
        }
        #pragma unroll
        for (int s = 0; s < 3; s++) {
            #pragma unroll
            for (int it = 0; it < 2; it++) {
                int lin = tid + it * 128;
                int nn = lin >> 2, k4 = (lin & 3) << 2;
                float4 v = *(const float4*)(Ws[s] + (long long)(n0 + nn) * C_ + c0 + k4);
                *(uint4*)(&Bs[s][nn * S_RK + k4]) = cvt4(v);
            }
        }
        __syncthreads();

        #pragma unroll
        for (int ks = 0; ks < 2; ks++) {
            const int kk = ks * 8;
            uint32_t af[2][4];
            #pragma unroll
            for (int i = 0; i < 2; i++) {
                int row = wm + i * 16;
                af[i][0] = As[(kk + tig)     * S_KM + row + gid];
                af[i][1] = As[(kk + tig)     * S_KM + row + gid + 8];
                af[i][2] = As[(kk + tig + 4) * S_KM + row + gid];
                af[i][3] = As[(kk + tig + 4) * S_KM + row + gid + 8];
            }
            #pragma unroll
            for (int s = 0; s < 3; s++) {
                uint32_t bf[4][2];
                #pragma unroll
                for (int j = 0; j < 4; j++) {
                    int col = wn + j * 8;
                    bf[j][0] = Bs[s][(col + gid) * S_RK + kk + tig];
                    bf[j][1] = Bs[s][(col + gid) * S_RK + kk + tig + 4];
                }
                #pragma unroll
                for (int i = 0; i < 2; i++)
                    #pragma unroll
                    for (int j = 0; j < 4; j++)
                        mma_tf32(acc[s][i][j][0], acc[s][i][j][1], acc[s][i][j][2], acc[s][i][j][3],
                                 af[i][0], af[i][1], af[i][2], af[i][3],
                                 bf[j][0], bf[j][1]);
            }
        }
        __syncthreads();
    }

    #pragma unroll
    for (int i = 0; i < 2; i++) {
        int grow = m0 + wm + i * 16 + gid;
        #pragma unroll
        for (int j = 0; j < 4; j++) {
            int gcol = n0 + wn + j * 8 + tig * 2;
            {
                float b0v = tb[gcol], b1v = tb[gcol + 1];
                *(float2*)(Q + (long long)grow * IC_ + gcol) =
                    make_float2(acc[0][i][j][0] + b0v, acc[0][i][j][1] + b1v);
                *(float2*)(Q + (long long)(grow + 8) * IC_ + gcol) =
                    make_float2(acc[0][i][j][2] + b0v, acc[0][i][j][3] + b1v);
            }
            {
                float b0v = pb[gcol], b1v = pb[gcol + 1];
                *(float2*)(K + (long long)grow * IC_ + gcol) =
                    make_float2(acc[1][i][j][0] + b0v, acc[1][i][j][1] + b1v);
                *(float2*)(K + (long long)(grow + 8) * IC_ + gcol) =
                    make_float2(acc[1][i][j][2] + b0v, acc[1][i][j][3] + b1v);
            }
            {
                float b0v = gb[gcol], b1v = gb[gcol + 1];
                Vt[(long long)gcol       * NP_ + grow]     = __float2half_rn(acc[2][i][j][0] + b0v);
                Vt[(long long)(gcol + 1) * NP_ + grow]     = __float2half_rn(acc[2][i][j][1] + b1v);
                Vt[(long long)gcol       * NP_ + grow + 8] = __float2half_rn(acc[2][i][j][2] + b0v);
                Vt[(long long)(gcol + 1) * NP_ + grow + 8] = __float2half_rn(acc[2][i][j][3] + b1v);
            }
        }
    }
}

// ===========================================================================
// y2 GEMM with FUSED BN statistics (sum / sumsq per channel via atomics)
// ===========================================================================
__global__ __launch_bounds__(128) void gemm_y2_stats(
    const float* __restrict__ A, const float* __restrict__ Bm,
    const float* __restrict__ bias, float* __restrict__ Cc,
    int K, int sA, int sB, int ldc, long long batA, long long batC)
{
    A  += (long long)blockIdx.z * batA;
    Cc += (long long)blockIdx.z * batC;

    const int m0 = blockIdx.x * BM;
    const int n0 = blockIdx.y * BN;
    const int tid = threadIdx.x;
    const int w = tid >> 5, lane = tid & 31;
    const int gid = lane >> 2, tig = lane & 3;
    const int wm = (w & 1) * 32, wn = (w >> 1) * 32;

    __shared__ uint32_t As[BM * S_RK];
    __shared__ uint32_t Bs[BN * S_RK];
    __shared__ float csum[BN];
    __shared__ float csq [BN];

    if (tid < BN) { csum[tid] = 0.f; csq[tid] = 0.f; }

    float acc[2][4][4];
    #pragma unroll
    for (int i = 0; i < 2; i++)
        #pragma unroll
        for (int j = 0; j < 4; j++)
            #pragma unroll
            for (int r = 0; r < 4; r++) acc[i][j][r] = 0.0f;

    for (int k0 = 0; k0 < K; k0 += BK) {
        #pragma unroll
        for (int it = 0; it < 2; it++) {
            int lin = tid + it * 128;
            int mm = lin >> 2, k4 = (lin & 3) << 2;
            float4 v = *(const float4*)(A + (long long)(m0 + mm) * sA + k0 + k4);
            *(uint4*)(&As[mm * S_RK + k4]) = cvt4(v);
        }
        #pragma unroll
        for (int it = 0; it < 2; it++) {
            int lin = tid + it * 128;
            int nn = lin >> 2, k4 = (lin & 3) << 2;
            float4 v = *(const float4*)(Bm + (long long)(n0 + nn) * sB + k0 + k4);
            *(uint4*)(&Bs[nn * S_RK + k4]) = cvt4(v);
        }
        __syncthreads();

        #pragma unroll
        for (int ks = 0; ks < 2; ks++) {
            const int kk = ks * 8;
            uint32_t af[2][4];
            #pragma unroll
            for (int i = 0; i < 2; i++) {
                int row = wm + i * 16;
                af[i][0] = As[(row + gid)     * S_RK + kk + tig];
                af[i][1] = As[(row + gid + 8) * S_RK + kk + tig];
                af[i][2] = As[(row + gid)     * S_RK + kk + tig + 4];
                af[i][3] = As[(row + gid + 8) * S_RK + kk + tig + 4];
            }
            uint32_t bf[4][2];
            #pragma unroll
            for (int j = 0; j < 4; j++) {
                int col = wn + j * 8;
                bf[j][0] = Bs[(col + gid) * S_RK + kk + tig];
                bf[j][1] = Bs[(col + gid) * S_RK + kk + tig + 4];
            }
            #pragma unroll
            for (int i = 0; i < 2; i++)
                #pragma unroll
                for (int j = 0; j < 4; j++)
                    mma_tf32(acc[i][j][0], acc[i][j][1], acc[i][j][2], acc[i][j][3],
                             af[i][0], af[i][1], af[i][2], af[i][3],
                             bf[j][0], bf[j][1]);
        }
        __syncthreads();
    }

    // epilogue: add bias, store, accumulate column partial sums
    #pragma unroll
    for (int j = 0; j < 4; j++) {
        int lcol = wn + j * 8 + tig * 2;
        int gcol = n0 + lcol;
        float b0v = bias[gcol], b1v = bias[gcol + 1];
        float s0 = 0.f, q0 = 0.f, s1 = 0.f, q1 = 0.f;
        #pragma unroll
        for (int i = 0; i < 2; i++) {
            int grow = m0 + wm + i * 16 + gid;
            float v00 = acc[i][j][0] + b0v;
            float v01 = acc[i][j][1] + b1v;
            float v10 = acc[i][j][2] + b0v;
            float v11 = acc[i][j][3] + b1v;
            *(float2*)(Cc + (long long)grow * ldc + gcol)       = make_float2(v00, v01);
            *(float2*)(Cc + (long long)(grow + 8) * ldc + gcol) = make_float2(v10, v11);
            s0 += v00 + v10;  q0 += v00 * v00 + v10 * v10;
            s1 += v01 + v11;  q1 += v01 * v01 + v11 * v11;
        }
        atomicAdd(&csum[lcol],     s0);
        atomicAdd(&csq [lcol],     q0);
        atomicAdd(&csum[lcol + 1], s1);
        atomicAdd(&csq [lcol + 1], q1);
    }
    __syncthreads();
    if (tid < BN) {
        atomicAdd(&g_sum  [n0 + tid], (double)csum[tid]);
        atomicAdd(&g_sumsq[n0 + tid], (double)csq [tid]);
    }
}

// ===========================================================================
// S = Q*K^T : 128x128x16 double-buffered tf32 (unchanged)
// ===========================================================================
constexpr int BM2 = 128, BN2 = 128, BK2 = 16;
constexpr int SRK2 = BK2 + 4;    // 20
constexpr int SBUF = BM2 * SRK2;

__global__ __launch_bounds__(256) void gemm_s(
    const float* __restrict__ A, const float* __restrict__ Bm,
    float* __restrict__ Cc)
{
    const long long z = blockIdx.z;
    A  += z * (long long)NP_ * IC_;
    Bm += z * (long long)NP_ * IC_;
    Cc += z * (long long)NP_ * NP_;

    const int m0 = blockIdx.x * BM2;
    const int n0 = blockIdx.y * BN2;
    const int tid = threadIdx.x;
    const int w = tid >> 5, lane = tid & 31;
    const int gid = lane >> 2, tig = lane & 3;
    const int wm = (w & 1) * 64, wn = (w >> 1) * 32;

    __shared__ uint32_t As[2][SBUF];
    __shared__ uint32_t Bs[2][SBUF];

    float acc[4][4][4];
    #pragma unroll
    for (int i = 0; i < 4; i++)
        #pragma unroll
        for (int j = 0; j < 4; j++)
            #pragma unroll
            for (int r = 0; r < 4; r++) acc[i][j][r] = 0.0f;

    float4 ra[2], rb[2];
    auto gload = [&](int k0) {
        #pragma unroll
        for (int it = 0; it < 2; it++) {
            int lin = tid + it * 256;
            int mm = lin >> 2, k4 = (lin & 3) << 2;
            ra[it] = *(const float4*)(A + (long long)(m0 + mm) * IC_ + k0 + k4);
            rb[it] = *(const float4*)(Bm + (long long)(n0 + mm) * IC_ + k0 + k4);
        }
    };
    auto sstore = [&](int b) {
        #pragma unroll
        for (int it = 0; it < 2; it++) {
            int lin = tid + it * 256;
            int mm = lin >> 2, k4 = (lin & 3) << 2;
            *(uint4*)(&As[b][mm * SRK2 + k4]) = cvt4(ra[it]);
            *(uint4*)(&Bs[b][mm * SRK2 + k4]) = cvt4(rb[it]);
        }
    };

    gload(0); sstore(0); __syncthreads();
    int buf = 0;
    for (int k0 = 0; k0 < IC_; k0 += BK2) {
        const bool nxt = (k0 + BK2 < IC_);
        if (nxt) gload(k0 + BK2);

        const uint32_t* Ab = As[buf];
        const uint32_t* Bb = Bs[buf];
        #pragma unroll
        for (int ks = 0; ks < 2; ks++) {
            const int kk = ks * 8;
            uint32_t af[4][4];
            #pragma unroll
            for (int i = 0; i < 4; i++) {
                int row = wm + i * 16;
                af[i][0] = Ab[(row + gid)     * SRK2 + kk + tig];
                af[i][1] = Ab[(row + gid + 8) * SRK2 + kk + tig];
                af[i][2] = Ab[(row + gid)     * SRK2 + kk + tig + 4];
                af[i][3] = Ab[(row + gid + 8) * SRK2 + kk + tig + 4];
            }
            uint32_t bf[4][2];
            #pragma unroll
            for (int j = 0; j < 4; j++) {
                int col = wn + j * 8;
                bf[j][0] = Bb[(col + gid) * SRK2 + kk + tig];
                bf[j][1] = Bb[(col + gid) * SRK2 + kk + tig + 4];
            }
            #pragma unroll
            for (int i = 0; i < 4; i++)
                #pragma unroll
                for (int j = 0; j < 4; j++)
                    mma_tf32(acc[i][j][0], acc[i][j][1], acc[i][j][2], acc[i][j][3],
                             af[i][0], af[i][1], af[i][2], af[i][3],
                             bf[j][0], bf[j][1]);
        }
        if (nxt) { sstore(buf ^ 1); __syncthreads(); buf ^= 1; }
    }

    #pragma unroll
    for (int i = 0; i < 4; i++) {
        int grow = m0 + wm + i * 16 + gid;
        #pragma unroll
        for (int j = 0; j < 4; j++) {
            int gcol = n0 + wn + j * 8 + tig * 2;
            *(float2*)(Cc + (long long)grow * NP_ + gcol) =
                make_float2(acc[i][j][0], acc[i][j][1]);
            *(float2*)(Cc + (long long)(grow + 8) * NP_ + gcol) =
                make_float2(acc[i][j][2], acc[i][j][3]);
        }
    }
}

// ===========================================================================
// y1 = P*V : fp16 mma (unchanged)
// ===========================================================================
constexpr int PVK = 32;
constexpr int PSTRW = 20;

__global__ __launch_bounds__(256) void pv_fp16(
    const __half* __restrict__ P, const __half* __restrict__ Vt,
    float* __restrict__ Y)
{
    const long long z = blockIdx.z;
    P  += z * (long long)NP_ * NP_;
    Vt += z * (long long)IC_ * NP_;
    Y  += z * (long long)NP_ * IC_;

    const int m0 = blockIdx.x * 128;
    const int n0 = blockIdx.y * 128;
    const int tid = threadIdx.x;
    const int w = tid >> 5, lane = tid & 31;
    const int gid = lane >> 2, tig = lane & 3;
    const int wm = (w & 1) * 64, wn = (w >> 1) * 32;

    __shared__ uint32_t Ps[2][128 * PSTRW];
    __shared__ uint32_t Vs[2][128 * PSTRW];

    float acc[4][4][4];
    #pragma unroll
    for (int i = 0; i < 4; i++)
        #pragma unroll
        for (int j = 0; j < 4; j++)
            #pragma unroll
            for (int r = 0; r < 4; r++) acc[i][j][r] = 0.0f;

    uint4 rp[2], rv[2];
    auto gload = [&](int k0) {
        #pragma unroll
        for (int it = 0; it < 2; it++) {
            int lin = tid + it * 256;
            int row = lin >> 2, k8 = (lin & 3) << 3;
            rp[it] = *(const uint4*)(P  + (long long)(m0 + row) * NP_ + k0 + k8);
            rv[it] = *(const uint4*)(Vt + (long long)(n0 + row) * NP_ + k0 + k8);
        }
    };
    auto sstore = [&](int b) {
        #pragma unroll
        for (int it = 0; it < 2; it++) {
            int lin = tid + it * 256;
            int row = lin >> 2, kw = (lin & 3) << 2;
            *(uint4*)(&Ps[b][row * PSTRW + kw]) = rp[it];
            *(uint4*)(&Vs[b][row * PSTRW + kw]) = rv[it];
        }
    };

    gload(0); sstore(0); __syncthreads();
    int buf = 0;
    for (int k0 = 0; k0 < N_; k0 += PVK) {
        const bool nxt = (k0 + PVK < N_);
        if (nxt) gload(k0 + PVK);

        const uint32_t* Pb = Ps[buf];
        const uint32_t* Vb = Vs[buf];
        #pragma unroll
        for (int ks = 0; ks < 2; ks++) {
            const int kc = ks * 8;
            uint32_t af[4][4];
            #pragma unroll
            for (int i = 0; i < 4; i++) {
                int row = wm + i * 16;
                af[i][0] = Pb[(row + gid)     * PSTRW + kc + tig];
                af[i][1] = Pb[(row + gid + 8) * PSTRW + kc + tig];
                af[i][2] = Pb[(row + gid)     * PSTRW + kc + tig + 4];
                af[i][3] = Pb[(row + gid + 8) * PSTRW + kc + tig + 4];
            }
            uint32_t bf[4][2];
            #pragma unroll
            for (int j = 0; j < 4; j++) {
                int col = wn + j * 8;
                bf[j][0] = Vb[(col + gid) * PSTRW + kc + tig];
                bf[j][1] = Vb[(col + gid) * PSTRW + kc + tig + 4];
            }
            #pragma unroll
            for (int i = 0; i < 4; i++)
                #pragma unroll
                for (int j = 0; j < 4; j++)
                    mma_f16(acc[i][j][0], acc[i][j][1], acc[i][j][2], acc[i][j][3],
                            af[i][0], af[i][1], af[i][2], af[i][3],
                            bf[j][0], bf[j][1]);
        }
        if (nxt) { sstore(buf ^ 1); __syncthreads(); buf ^= 1; }
    }

    #pragma unroll
    for (int i = 0; i < 4; i++) {
        int grow = m0 + wm + i * 16 + gid;
        #pragma unroll
        for (int j = 0; j < 4; j++) {
            int gcol = n0 + wn + j * 8 + tig * 2;
            *(float2*)(Y + (long long)grow * IC_ + gcol) =
                make_float2(acc[i][j][0], acc[i][j][1]);
            *(float2*)(Y + (long long)(grow + 8) * IC_ + gcol) =
                make_float2(acc[i][j][2], acc[i][j][3]);
        }
    }
}

// ---------------------------------------------------------------------------
// Row softmax v2: float4 + warp shuffles + MUFU exp; 2 syncthreads total.
// grid (N_, B_), block 256.
// ---------------------------------------------------------------------------
#define NF4 (N_ / 4)   // 784 float4 per row

__global__ __launch_bounds__(256) void softmax_rows(
    const float* __restrict__ S, __half* __restrict__ P)
{
    __shared__ float buf[N_];
    __shared__ float wredm[8];
    __shared__ float wreds[8];
    const float* row = S + (size_t)blockIdx.y * NP_ * NP_ + (size_t)blockIdx.x * NP_;
    __half* prow     = P + (size_t)blockIdx.y * NP_ * NP_ + (size_t)blockIdx.x * NP_;
    const int tid = threadIdx.x;
    const int wid = tid >> 5, lane = tid & 31;

    // pass 1: load to SMEM, thread-local max
    float m = -1e30f;
    for (int i4 = tid; i4 < NF4; i4 += 256) {
        float4 v = ((const float4*)row)[i4];
        ((float4*)buf)[i4] = v;
        m = fmaxf(fmaxf(m, fmaxf(v.x, v.y)), fmaxf(v.z, v.w));
    }
    #pragma unroll
    for (int o = 16; o > 0; o >>= 1) m = fmaxf(m, __shfl_xor_sync(~0u, m, o));
    if (lane == 0) wredm[wid] = m;
    __syncthreads();
    m = wredm[0];
    #pragma unroll
    for (int k = 1; k < 8; k++) m = fmaxf(m, wredm[k]);

    // pass 2: exp (MUFU) + sum; each thread touches only its own SMEM words
    float sum = 0.f;
    for (int i4 = tid; i4 < NF4; i4 += 256) {
        float4 v = ((const float4*)buf)[i4];
        v.x = __expf(v.x - m); v.y = __expf(v.y - m);
        v.z = __expf(v.z - m); v.w = __expf(v.w - m);
        ((float4*)buf)[i4] = v;
        sum += (v.x + v.y) + (v.z + v.w);
    }
    #pragma unroll
    for (int o = 16; o > 0; o >>= 1) sum += __shfl_xor_sync(~0u, sum, o);
    if (lane == 0) wreds[wid] = sum;
    __syncthreads();
    sum = wreds[0];
    #pragma unroll
    for (int k = 1; k < 8; k++) sum += wreds[k];
    const float inv = 1.0f / sum;

    // pass 3: normalize + fp16 store (8B per thread-iter)
    for (int i4 = tid; i4 < NF4; i4 += 256) {
        float4 v = ((const float4*)buf)[i4];
        uint2 o;
        __half2 h0 = __floats2half2_rn(v.x * inv, v.y * inv);
        __half2 h1 = __floats2half2_rn(v.z * inv, v.w * inv);
        o.x = *(uint32_t*)&h0;
        o.y = *(uint32_t*)&h1;
        ((uint2*)prow)[i4] = o;
    }
}

// ---------------------------------------------------------------------------
// BN: zero stats + final normalize/residual/transpose
// ---------------------------------------------------------------------------
__global__ void zero_stats()
{
    int t = threadIdx.x;   // 512 threads
    g_sum[t] = 0.0;
    g_sumsq[t] = 0.0;
}

__global__ __launch_bounds__(256) void bn_final(
    const float* __restrict__ x,
    const float* __restrict__ bn_w, const float* __restrict__ bn_b,
    float* __restrict__ out)
{
    __shared__ float t[32][33];
    const int b  = blockIdx.z;
    const int c0 = blockIdx.y * 32;
    const int n0 = blockIdx.x * 32;
    const int tx = threadIdx.x, ty = threadIdx.y;

    #pragma unroll
    for (int j = 0; j < 32; j += 8) {
        int n = n0 + ty + j;
        t[ty + j][tx] = g_y2[((size_t)(b * N_ + n)) * C_ + c0 + tx];
    }
    __syncthreads();

    const double cnt = (double)ROWS_TOTAL;
    #pragma unroll
    for (int j = 0; j < 32; j += 8) {
        int c = c0 + ty + j;
        double mean = g_sum[c] / cnt;
        double var  = g_sumsq[c] / cnt - mean * mean;
        float inv = (float)rsqrt(var + 1e-5);
        float w = bn_w[c], bb = bn_b[c];
        int n = n0 + tx;
        size_t oidx = ((size_t)b * C_ + c) * (size_t)N_ + n;
        float v = t[tx][ty + j];
        out[oidx] = (v - (float)mean) * inv * w + bb + x[oidx];
    }
}

// ---------------------------------------------------------------------------
// Launch
// ---------------------------------------------------------------------------
extern "C" void kernel_launch(void* const* d_in, const int* in_sizes, int n_in,
                              void* d_out, int out_size)
{
    const float* x       = (const float*)d_in[0];
    const float* theta_w = (const float*)d_in[1];
    const float* theta_b = (const float*)d_in[2];
    const float* phi_w   = (const float*)d_in[3];
    const float* phi_b   = (const float*)d_in[4];
    const float* gw      = (const float*)d_in[5];
    const float* gb      = (const float*)d_in[6];
    const float* wz_w    = (const float*)d_in[7];
    const float* wz_b    = (const float*)d_in[8];
    const float* bn_w    = (const float*)d_in[9];
    const float* bn_b    = (const float*)d_in[10];
    float* out = (float*)d_out;

    float *Q, *K, *S, *y1, *y2;
    __half *Vt, *P;
    cudaGetSymbolAddress((void**)&Q,  g_Q);
    cudaGetSymbolAddress((void**)&K,  g_K);
    cudaGetSymbolAddress((void**)&Vt, g_Vt);
    cudaGetSymbolAddress((void**)&S,  g_S);
    cudaGetSymbolAddress((void**)&P,  g_P);
    cudaGetSymbolAddress((void**)&y1, g_y1);
    cudaGetSymbolAddress((void**)&y2, g_y2);

    zero_stats<<<1, 512>>>();

    // fused QKV projections
    qkv_fused<<<dim3(N_ / BM, IC_ / BN, B_), 128>>>(
        x, theta_w, theta_b, phi_w, phi_b, gw, gb, Q, K, Vt);

    // S = Q K^T (tf32, 128x128 double-buffered)
    gemm_s<<<dim3(NP_ / BM2, NP_ / BN2, B_), 256>>>(Q, K, S);

    // softmax rows -> fp16 probs
    softmax_rows<<<dim3(N_, B_), 256>>>(S, P);

    // y1 = P V (fp16 mma)
    pv_fp16<<<dim3(NP_ / 128, IC_ / 128, B_), 256>>>(P, Vt, y1);

    // y2 = y1 Wz^T + b (tf32) with fused BN statistics
    gemm_y2_stats<<<dim3(N_ / BM, C_ / BN, B_), 128>>>(y1, wz_w, wz_b, y2,
        IC_, IC_, IC_, C_, (long long)NP_ * IC_, (long long)N_ * C_);

    // BN normalize + residual + transpose
    bn_final<<<dim3(N_ / 32, C_ / 32, B_), dim3(32, 8)>>>(x, bn_w, bn_b, out);
}

// round 8
// speedup vs baseline: 3.0481x; 1.1858x over previous
#include <cuda_runtime.h>
#include <cuda_fp16.h>
#include <math.h>
#include <stdint.h>

// Problem constants
#define B_   8
#define C_   512
#define N_   3136   // 56*56
#define NP_  3200   // N padded to multiple of 128
#define IC_  256
#define ROWS_TOTAL (B_ * N_)   // 25088

// ---------------------------------------------------------------------------
// Scratch
// ---------------------------------------------------------------------------
__device__ __half g_Qh[(size_t)B_ * NP_ * IC_];   // Q fp16 [token][i]
__device__ __half g_Kh[(size_t)B_ * NP_ * IC_];   // K fp16 [token][i]
__device__ __half g_Vt[(size_t)B_ * IC_ * NP_];   // V fp16 transposed [i][token]
__device__ float  g_S [(size_t)B_ * NP_ * NP_];   // logits fp32
__device__ __half g_P [(size_t)B_ * NP_ * NP_];   // softmax probs fp16
__device__ float  g_y1[(size_t)B_ * NP_ * IC_];
__device__ float  g_y2[(size_t)B_ * N_ * C_];
__device__ double g_sum[C_];
__device__ double g_sumsq[C_];

// ---------------------------------------------------------------------------
// mma helpers
// ---------------------------------------------------------------------------
__device__ __forceinline__ uint32_t f2tf32(float x) {
    uint32_t u;
    asm("cvt.rna.tf32.f32 %0, %1;" : "=r"(u) : "f"(x));
    return u;
}
__device__ __forceinline__ uint4 cvt4(float4 v) {
    return make_uint4(f2tf32(v.x), f2tf32(v.y), f2tf32(v.z), f2tf32(v.w));
}
__device__ __forceinline__ void mma_tf32(float& d0, float& d1, float& d2, float& d3,
                                         uint32_t a0, uint32_t a1, uint32_t a2, uint32_t a3,
                                         uint32_t b0, uint32_t b1) {
    asm volatile(
        "mma.sync.aligned.m16n8k8.row.col.f32.tf32.tf32.f32 "
        "{%0,%1,%2,%3}, {%4,%5,%6,%7}, {%8,%9}, {%0,%1,%2,%3};\n"
        : "+f"(d0), "+f"(d1), "+f"(d2), "+f"(d3)
        : "r"(a0), "r"(a1), "r"(a2), "r"(a3), "r"(b0), "r"(b1));
}
__device__ __forceinline__ void mma_f16(float& d0, float& d1, float& d2, float& d3,
                                        uint32_t a0, uint32_t a1, uint32_t a2, uint32_t a3,
                                        uint32_t b0, uint32_t b1) {
    asm volatile(
        "mma.sync.aligned.m16n8k16.row.col.f32.f16.f16.f32 "
        "{%0,%1,%2,%3}, {%4,%5,%6,%7}, {%8,%9}, {%0,%1,%2,%3};\n"
        : "+f"(d0), "+f"(d1), "+f"(d2), "+f"(d3)
        : "r"(a0), "r"(a1), "r"(a2), "r"(a3), "r"(b0), "r"(b1));
}

// ===========================================================================
// Fused QKV projection. Writes Q, K fp16 row-major [token][i]; V fp16
// transposed [i][token].
// ===========================================================================
constexpr int BM = 64, BN = 64, BK = 16;
constexpr int S_RK = BK + 4;   // 20
constexpr int S_KM = BM + 8;   // 72

__global__ __launch_bounds__(128) void qkv_fused(
    const float* __restrict__ x,
    const float* __restrict__ tw, const float* __restrict__ tb,
    const float* __restrict__ pw, const float* __restrict__ pb,
    const float* __restrict__ gw, const float* __restrict__ gb,
    __half* __restrict__ Q, __half* __restrict__ K, __half* __restrict__ Vt)
{
    const long long z = blockIdx.z;
    x  += z * (long long)C_ * N_;
    Q  += z * (long long)NP_ * IC_;
    K  += z * (long long)NP_ * IC_;
    Vt += z * (long long)IC_ * NP_;

    const int m0 = blockIdx.x * BM;
    const int n0 = blockIdx.y * BN;
    const int tid = threadIdx.x;
    const int w = tid >> 5, lane = tid & 31;
    const int gid = lane >> 2, tig = lane & 3;
    const int wm = (w & 1) * 32, wn = (w >> 1) * 32;

    __shared__ uint32_t As[BK * S_KM];
    __shared__ uint32_t Bs[3][BN * S_RK];

    const float* Ws[3] = {tw, pw, gw};

    float acc[3][2][4][4];
    #pragma unroll
    for (int s = 0; s < 3; s++)
        #pragma unroll
        for (int i = 0; i < 2; i++)
            #pragma unroll
            for (int j = 0; j < 4; j++)
                #pragma unroll
                for (int r = 0; r < 4; r++) acc[s][i][j][r] = 0.0f;

    for (int c0 = 0; c0 < C_; c0 += BK) {
        #pragma unroll
        for (int it = 0; it < 2; it++) {
            int lin = tid + it * 128;
            int kk = lin >> 4, m4 = (lin & 15) << 2;
            float4 v = *(const float4*)(x + (long long)(c0 + kk) * N_ + m0 + m4);
            *(uint4*)(&As[kk * S_KM + m4]) = cvt4(v);
        }
        #pragma unroll
        for (int s = 0; s < 3; s++) {
            #pragma unroll
            for (int it = 0; it < 2; it++) {
                int lin = tid + it * 128;
                int nn = lin >> 2, k4 = (lin & 3) << 2;
                float4 v = *(const float4*)(Ws[s] + (long long)(n0 + nn) * C_ + c0 + k4);
                *(uint4*)(&Bs[s][nn * S_RK + k4]) = cvt4(v);
            }
        }
        __syncthreads();

        #pragma unroll
        for (int ks = 0; ks < 2; ks++) {
            const int kk = ks * 8;
            uint32_t af[2][4];
            #pragma unroll
            for (int i = 0; i < 2; i++) {
                int row = wm + i * 16;
                af[i][0] = As[(kk + tig)     * S_KM + row + gid];
                af[i][1] = As[(kk + tig)     * S_KM + row + gid + 8];
                af[i][2] = As[(kk + tig + 4) * S_KM + row + gid];
                af[i][3] = As[(kk + tig + 4) * S_KM + row + gid + 8];
            }
            #pragma unroll
            for (int s = 0; s < 3; s++) {
                uint32_t bf[4][2];
                #pragma unroll
                for (int j = 0; j < 4; j++) {
                    int col = wn + j * 8;
                    bf[j][0] = Bs[s][(col + gid) * S_RK + kk + tig];
                    bf[j][1] = Bs[s][(col + gid) * S_RK + kk + tig + 4];
                }
                #pragma unroll
                for (int i = 0; i < 2; i++)
                    #pragma unroll
                    for (int j = 0; j < 4; j++)
                        mma_tf32(acc[s][i][j][0], acc[s][i][j][1], acc[s][i][j][2], acc[s][i][j][3],
                                 af[i][0], af[i][1], af[i][2], af[i][3],
                                 bf[j][0], bf[j][1]);
            }
        }
        __syncthreads();
    }

    #pragma unroll
    for (int i = 0; i < 2; i++) {
        int grow = m0 + wm + i * 16 + gid;
        #pragma unroll
        for (int j = 0; j < 4; j++) {
            int gcol = n0 + wn + j * 8 + tig * 2;
            // Q fp16
            {
                float b0v = tb[gcol], b1v = tb[gcol + 1];
                *(__half2*)(Q + (long long)grow * IC_ + gcol) =
                    __floats2half2_rn(acc[0][i][j][0] + b0v, acc[0][i][j][1] + b1v);
                *(__half2*)(Q + (long long)(grow + 8) * IC_ + gcol) =
                    __floats2half2_rn(acc[0][i][j][2] + b0v, acc[0][i][j][3] + b1v);
            }
            // K fp16
            {
                float b0v = pb[gcol], b1v = pb[gcol + 1];
                *(__half2*)(K + (long long)grow * IC_ + gcol) =
                    __floats2half2_rn(acc[1][i][j][0] + b0v, acc[1][i][j][1] + b1v);
                *(__half2*)(K + (long long)(grow + 8) * IC_ + gcol) =
                    __floats2half2_rn(acc[1][i][j][2] + b0v, acc[1][i][j][3] + b1v);
            }
            // V fp16 transposed
            {
                float b0v = gb[gcol], b1v = gb[gcol + 1];
                Vt[(long long)gcol       * NP_ + grow]     = __float2half_rn(acc[2][i][j][0] + b0v);
                Vt[(long long)(gcol + 1) * NP_ + grow]     = __float2half_rn(acc[2][i][j][1] + b1v);
                Vt[(long long)gcol       * NP_ + grow + 8] = __float2half_rn(acc[2][i][j][2] + b0v);
                Vt[(long long)(gcol + 1) * NP_ + grow + 8] = __float2half_rn(acc[2][i][j][3] + b1v);
            }
        }
    }
}

// ===========================================================================
// y2 GEMM with fused BN statistics
// ===========================================================================
__global__ __launch_bounds__(128) void gemm_y2_stats(
    const float* __restrict__ A, const float* __restrict__ Bm,
    const float* __restrict__ bias, float* __restrict__ Cc,
    int K, int sA, int sB, int ldc, long long batA, long long batC)
{
    A  += (long long)blockIdx.z * batA;
    Cc += (long long)blockIdx.z * batC;

    const int m0 = blockIdx.x * BM;
    const int n0 = blockIdx.y * BN;
    const int tid = threadIdx.x;
    const int w = tid >> 5, lane = tid & 31;
    const int gid = lane >> 2, tig = lane & 3;
    const int wm = (w & 1) * 32, wn = (w >> 1) * 32;

    __shared__ uint32_t As[BM * S_RK];
    __shared__ uint32_t Bs[BN * S_RK];
    __shared__ float csum[BN];
    __shared__ float csq [BN];

    if (tid < BN) { csum[tid] = 0.f; csq[tid] = 0.f; }

    float acc[2][4][4];
    #pragma unroll
    for (int i = 0; i < 2; i++)
        #pragma unroll
        for (int j = 0; j < 4; j++)
            #pragma unroll
            for (int r = 0; r < 4; r++) acc[i][j][r] = 0.0f;

    for (int k0 = 0; k0 < K; k0 += BK) {
        #pragma unroll
        for (int it = 0; it < 2; it++) {
            int lin = tid + it * 128;
            int mm = lin >> 2, k4 = (lin & 3) << 2;
            float4 v = *(const float4*)(A + (long long)(m0 + mm) * sA + k0 + k4);
            *(uint4*)(&As[mm * S_RK + k4]) = cvt4(v);
        }
        #pragma unroll
        for (int it = 0; it < 2; it++) {
            int lin = tid + it * 128;
            int nn = lin >> 2, k4 = (lin & 3) << 2;
            float4 v = *(const float4*)(Bm + (long long)(n0 + nn) * sB + k0 + k4);
            *(uint4*)(&Bs[nn * S_RK + k4]) = cvt4(v);
        }
        __syncthreads();

        #pragma unroll
        for (int ks = 0; ks < 2; ks++) {
            const int kk = ks * 8;
            uint32_t af[2][4];
            #pragma unroll
            for (int i = 0; i < 2; i++) {
                int row = wm + i * 16;
                af[i][0] = As[(row + gid)     * S_RK + kk + tig];
                af[i][1] = As[(row + gid + 8) * S_RK + kk + tig];
                af[i][2] = As[(row + gid)     * S_RK + kk + tig + 4];
                af[i][3] = As[(row + gid + 8) * S_RK + kk + tig + 4];
            }
            uint32_t bf[4][2];
            #pragma unroll
            for (int j = 0; j < 4; j++) {
                int col = wn + j * 8;
                bf[j][0] = Bs[(col + gid) * S_RK + kk + tig];
                bf[j][1] = Bs[(col + gid) * S_RK + kk + tig + 4];
            }
            #pragma unroll
            for (int i = 0; i < 2; i++)
                #pragma unroll
                for (int j = 0; j < 4; j++)
                    mma_tf32(acc[i][j][0], acc[i][j][1], acc[i][j][2], acc[i][j][3],
                             af[i][0], af[i][1], af[i][2], af[i][3],
                             bf[j][0], bf[j][1]);
        }
        __syncthreads();
    }

    #pragma unroll
    for (int j = 0; j < 4; j++) {
        int lcol = wn + j * 8 + tig * 2;
        int gcol = n0 + lcol;
        float b0v = bias[gcol], b1v = bias[gcol + 1];
        float s0 = 0.f, q0 = 0.f, s1 = 0.f, q1 = 0.f;
        #pragma unroll
        for (int i = 0; i < 2; i++) {
            int grow = m0 + wm + i * 16 + gid;
            float v00 = acc[i][j][0] + b0v;
            float v01 = acc[i][j][1] + b1v;
            float v10 = acc[i][j][2] + b0v;
            float v11 = acc[i][j][3] + b1v;
            *(float2*)(Cc + (long long)grow * ldc + gcol)       = make_float2(v00, v01);
            *(float2*)(Cc + (long long)(grow + 8) * ldc + gcol) = make_float2(v10, v11);
            s0 += v00 + v10;  q0 += v00 * v00 + v10 * v10;
            s1 += v01 + v11;  q1 += v01 * v01 + v11 * v11;
        }
        atomicAdd(&csum[lcol],     s0);
        atomicAdd(&csq [lcol],     q0);
        atomicAdd(&csum[lcol + 1], s1);
        atomicAdd(&csq [lcol + 1], q1);
    }
    __syncthreads();
    if (tid < BN) {
        atomicAdd(&g_sum  [n0 + tid], (double)csum[tid]);
        atomicAdd(&g_sumsq[n0 + tid], (double)csq [tid]);
    }
}

// ===========================================================================
// Generic fp16 mma GEMM, 128x128x32 double-buffered, fp32 output.
// A [m][k] fp16 k-contig stride sA; B [n][k] fp16 k-contig stride sB.
// Used for S = Qh*Kh^T (K=IC_) and y1 = P*Vt^T (K=N_).
// ===========================================================================
constexpr int FK  = 32;        // k halves per iter
constexpr int FSTR = 20;       // 40 halves = 20 words per SMEM row

__global__ __launch_bounds__(256) void gemm_f16(
    const __half* __restrict__ A, const __half* __restrict__ Bm,
    float* __restrict__ Cc,
    int K, int sA, int sB, int ldc,
    long long batA, long long batB, long long batC)
{
    const long long z = blockIdx.z;
    A  += z * batA;
    Bm += z * batB;
    Cc += z * batC;

    const int m0 = blockIdx.x * 128;
    const int n0 = blockIdx.y * 128;
    const int tid = threadIdx.x;
    const int w = tid >> 5, lane = tid & 31;
    const int gid = lane >> 2, tig = lane & 3;
    const int wm = (w & 1) * 64, wn = (w >> 1) * 32;

    __shared__ uint32_t As[2][128 * FSTR];
    __shared__ uint32_t Bs[2][128 * FSTR];

    float acc[4][4][4];
    #pragma unroll
    for (int i = 0; i < 4; i++)
        #pragma unroll
        for (int j = 0; j < 4; j++)
            #pragma unroll
            for (int r = 0; r < 4; r++) acc[i][j][r] = 0.0f;

    uint4 ra[2], rb[2];
    auto gload = [&](int k0) {
        #pragma unroll
        for (int it = 0; it < 2; it++) {
            int lin = tid + it * 256;
            int row = lin >> 2, k8 = (lin & 3) << 3;
            ra[it] = *(const uint4*)(A  + (long long)(m0 + row) * sA + k0 + k8);
            rb[it] = *(const uint4*)(Bm + (long long)(n0 + row) * sB + k0 + k8);
        }
    };
    auto sstore = [&](int b) {
        #pragma unroll
        for (int it = 0; it < 2; it++) {
            int lin = tid + it * 256;
            int row = lin >> 2, kw = (lin & 3) << 2;
            *(uint4*)(&As[b][row * FSTR + kw]) = ra[it];
            *(uint4*)(&Bs[b][row * FSTR + kw]) = rb[it];
        }
    };

    gload(0); sstore(0); __syncthreads();
    int buf = 0;
    for (int k0 = 0; k0 < K; k0 += FK) {
        const bool nxt = (k0 + FK < K);
        if (nxt) gload(k0 + FK);

        const uint32_t* Ab = As[buf];
        const uint32_t* Bb = Bs[buf];
        #pragma unroll
        for (int ks = 0; ks < 2; ks++) {
            const int kc = ks * 8;
            uint32_t af[4][4];
            #pragma unroll
            for (int i = 0; i < 4; i++) {
                int row = wm + i * 16;
                af[i][0] = Ab[(row + gid)     * FSTR + kc + tig];
                af[i][1] = Ab[(row + gid + 8) * FSTR + kc + tig];
                af[i][2] = Ab[(row + gid)     * FSTR + kc + tig + 4];
                af[i][3] = Ab[(row + gid + 8) * FSTR + kc + tig + 4];
            }
            uint32_t bf[4][2];
            #pragma unroll
            for (int j = 0; j < 4; j++) {
                int col = wn + j * 8;
                bf[j][0] = Bb[(col + gid) * FSTR + kc + tig];
                bf[j][1] = Bb[(col + gid) * FSTR + kc + tig + 4];
            }
            #pragma unroll
            for (int i = 0; i < 4; i++)
                #pragma unroll
                for (int j = 0; j < 4; j++)
                    mma_f16(acc[i][j][0], acc[i][j][1], acc[i][j][2], acc[i][j][3],
                            af[i][0], af[i][1], af[i][2], af[i][3],
                            bf[j][0], bf[j][1]);
        }
        if (nxt) { sstore(buf ^ 1); __syncthreads(); buf ^= 1; }
    }

    #pragma unroll
    for (int i = 0; i < 4; i++) {
        int grow = m0 + wm + i * 16 + gid;
        #pragma unroll
        for (int j = 0; j < 4; j++) {
            int gcol = n0 + wn + j * 8 + tig * 2;
            *(float2*)(Cc + (long long)grow * ldc + gcol) =
                make_float2(acc[i][j][0], acc[i][j][1]);
            *(float2*)(Cc + (long long)(grow + 8) * ldc + gcol) =
                make_float2(acc[i][j][2], acc[i][j][3]);
        }
    }
}

// ---------------------------------------------------------------------------
// Row softmax: float4 + warp shuffles + MUFU exp
// ---------------------------------------------------------------------------
#define NF4 (N_ / 4)   // 784 float4 per row

__global__ __launch_bounds__(256) void softmax_rows(
    const float* __restrict__ S, __half* __restrict__ P)
{
    __shared__ float buf[N_];
    __shared__ float wredm[8];
    __shared__ float wreds[8];
    const float* row = S + (size_t)blockIdx.y * NP_ * NP_ + (size_t)blockIdx.x * NP_;
    __half* prow     = P + (size_t)blockIdx.y * NP_ * NP_ + (size_t)blockIdx.x * NP_;
    const int tid = threadIdx.x;
    const int wid = tid >> 5, lane = tid & 31;

    float m = -1e30f;
    for (int i4 = tid; i4 < NF4; i4 += 256) {
        float4 v = ((const float4*)row)[i4];
        ((float4*)buf)[i4] = v;
        m = fmaxf(fmaxf(m, fmaxf(v.x, v.y)), fmaxf(v.z, v.w));
    }
    #pragma unroll
    for (int o = 16; o > 0; o >>= 1) m = fmaxf(m, __shfl_xor_sync(~0u, m, o));
    if (lane == 0) wredm[wid] = m;
    __syncthreads();
    m = wredm[0];
    #pragma unroll
    for (int k = 1; k < 8; k++) m = fmaxf(m, wredm[k]);

    float sum = 0.f;
    for (int i4 = tid; i4 < NF4; i4 += 256) {
        float4 v = ((const float4*)buf)[i4];
        v.x = __expf(v.x - m); v.y = __expf(v.y - m);
        v.z = __expf(v.z - m); v.w = __expf(v.w - m);
        ((float4*)buf)[i4] = v;
        sum += (v.x + v.y) + (v.z + v.w);
    }
    #pragma unroll
    for (int o = 16; o > 0; o >>= 1) sum += __shfl_xor_sync(~0u, sum, o);
    if (lane == 0) wreds[wid] = sum;
    __syncthreads();
    sum = wreds[0];
    #pragma unroll
    for (int k = 1; k < 8; k++) sum += wreds[k];
    const float inv = 1.0f / sum;

    for (int i4 = tid; i4 < NF4; i4 += 256) {
        float4 v = ((const float4*)buf)[i4];
        uint2 o;
        __half2 h0 = __floats2half2_rn(v.x * inv, v.y * inv);
        __half2 h1 = __floats2half2_rn(v.z * inv, v.w * inv);
        o.x = *(uint32_t*)&h0;
        o.y = *(uint32_t*)&h1;
        ((uint2*)prow)[i4] = o;
    }
}

// ---------------------------------------------------------------------------
// BN: zero stats + final normalize/residual/transpose
// ---------------------------------------------------------------------------
__global__ void zero_stats()
{
    int t = threadIdx.x;   // 512 threads
    g_sum[t] = 0.0;
    g_sumsq[t] = 0.0;
}

__global__ __launch_bounds__(256) void bn_final(
    const float* __restrict__ x,
    const float* __restrict__ bn_w, const float* __restrict__ bn_b,
    float* __restrict__ out)
{
    __shared__ float t[32][33];
    const int b  = blockIdx.z;
    const int c0 = blockIdx.y * 32;
    const int n0 = blockIdx.x * 32;
    const int tx = threadIdx.x, ty = threadIdx.y;

    #pragma unroll
    for (int j = 0; j < 32; j += 8) {
        int n = n0 + ty + j;
        t[ty + j][tx] = g_y2[((size_t)(b * N_ + n)) * C_ + c0 + tx];
    }
    __syncthreads();

    const double cnt = (double)ROWS_TOTAL;
    #pragma unroll
    for (int j = 0; j < 32; j += 8) {
        int c = c0 + ty + j;
        double mean = g_sum[c] / cnt;
        double var  = g_sumsq[c] / cnt - mean * mean;
        float inv = (float)rsqrt(var + 1e-5);
        float w = bn_w[c], bb = bn_b[c];
        int n = n0 + tx;
        size_t oidx = ((size_t)b * C_ + c) * (size_t)N_ + n;
        float v = t[tx][ty + j];
        out[oidx] = (v - (float)mean) * inv * w + bb + x[oidx];
    }
}

// ---------------------------------------------------------------------------
// Launch
// ---------------------------------------------------------------------------
extern "C" void kernel_launch(void* const* d_in, const int* in_sizes, int n_in,
                              void* d_out, int out_size)
{
    const float* x       = (const float*)d_in[0];
    const float* theta_w = (const float*)d_in[1];
    const float* theta_b = (const float*)d_in[2];
    const float* phi_w   = (const float*)d_in[3];
    const float* phi_b   = (const float*)d_in[4];
    const float* gw      = (const float*)d_in[5];
    const float* gb      = (const float*)d_in[6];
    const float* wz_w    = (const float*)d_in[7];
    const float* wz_b    = (const float*)d_in[8];
    const float* bn_w    = (const float*)d_in[9];
    const float* bn_b    = (const float*)d_in[10];
    float* out = (float*)d_out;

    float *S, *y1, *y2;
    __half *Qh, *Kh, *Vt, *P;
    cudaGetSymbolAddress((void**)&Qh, g_Qh);
    cudaGetSymbolAddress((void**)&Kh, g_Kh);
    cudaGetSymbolAddress((void**)&Vt, g_Vt);
    cudaGetSymbolAddress((void**)&S,  g_S);
    cudaGetSymbolAddress((void**)&P,  g_P);
    cudaGetSymbolAddress((void**)&y1, g_y1);
    cudaGetSymbolAddress((void**)&y2, g_y2);

    zero_stats<<<1, 512>>>();

    // fused QKV projections (fp16 outputs)
    qkv_fused<<<dim3(N_ / BM, IC_ / BN, B_), 128>>>(
        x, theta_w, theta_b, phi_w, phi_b, gw, gb, Qh, Kh, Vt);

    // S = Qh Kh^T (fp16 mma, fp32 out)
    gemm_f16<<<dim3(NP_ / 128, NP_ / 128, B_), 256>>>(Qh, Kh, S,
        IC_, IC_, IC_, NP_,
        (long long)NP_ * IC_, (long long)NP_ * IC_, (long long)NP_ * NP_);

    // softmax rows -> fp16 probs
    softmax_rows<<<dim3(N_, B_), 256>>>(S, P);

    // y1 = P Vt^T (fp16 mma)
    gemm_f16<<<dim3(NP_ / 128, IC_ / 128, B_), 256>>>(P, Vt, y1,
        N_, NP_, NP_, IC_,
        (long long)NP_ * NP_, (long long)IC_ * NP_, (long long)NP_ * IC_);

    // y2 = y1 Wz^T + b (tf32) with fused BN statistics
    gemm_y2_stats<<<dim3(N_ / BM, C_ / BN, B_), 128>>>(y1, wz_w, wz_b, y2,
        IC_, IC_, IC_, C_, (long long)NP_ * IC_, (long long)N_ * C_);

    // BN normalize + residual + transpose
    bn_final<<<dim3(N_ / 32, C_ / 32, B_), dim3(32, 8)>>>(x, bn_w, bn_b, out);
}

// round 9
// speedup vs baseline: 3.4233x; 1.1231x over previous
#include <cuda_runtime.h>
#include <cuda_fp16.h>
#include <math.h>
#include <stdint.h>

// Problem constants
#define B_   8
#define C_   512
#define N_   3136   // 56*56
#define NP_  3200   // N padded to multiple of 128
#define IC_  256
#define ROWS_TOTAL (B_ * N_)   // 25088

// ---------------------------------------------------------------------------
// Scratch
// ---------------------------------------------------------------------------
__device__ __half g_xh [(size_t)B_ * NP_ * C_];   // x fp16 transposed [token][c]
__device__ __half g_Wh [(size_t)3 * IC_ * C_];    // theta/phi/g weights fp16
__device__ __half g_wzh[(size_t)C_ * IC_];        // wz fp16
__device__ __half g_Qh [(size_t)B_ * NP_ * IC_];  // Q fp16 [token][i]
__device__ __half g_Kh [(size_t)B_ * NP_ * IC_];  // K fp16 [token][i]
__device__ __half g_Vt [(size_t)B_ * IC_ * NP_];  // V fp16 transposed [i][token]
__device__ float  g_S  [(size_t)B_ * NP_ * NP_];  // logits fp32
__device__ __half g_P  [(size_t)B_ * NP_ * NP_];  // softmax probs fp16
__device__ __half g_y1h[(size_t)B_ * NP_ * IC_];  // attention out fp16
__device__ float  g_y2 [(size_t)B_ * N_ * C_];
__device__ double g_sum[C_];
__device__ double g_sumsq[C_];

// ---------------------------------------------------------------------------
// mma helper (fp16, fp32 accum)
// ---------------------------------------------------------------------------
__device__ __forceinline__ void mma_f16(float& d0, float& d1, float& d2, float& d3,
                                        uint32_t a0, uint32_t a1, uint32_t a2, uint32_t a3,
                                        uint32_t b0, uint32_t b1) {
    asm volatile(
        "mma.sync.aligned.m16n8k16.row.col.f32.f16.f16.f32 "
        "{%0,%1,%2,%3}, {%4,%5,%6,%7}, {%8,%9}, {%0,%1,%2,%3};\n"
        : "+f"(d0), "+f"(d1), "+f"(d2), "+f"(d3)
        : "r"(a0), "r"(a1), "r"(a2), "r"(a3), "r"(b0), "r"(b1));
}

constexpr int FSTR = 20;   // 40 halves (32 data + 8 pad) = 20 words per SMEM row

// ---------------------------------------------------------------------------
// Prep: convert weights to fp16 (same layout)
// ---------------------------------------------------------------------------
__global__ void conv_weights(const float* __restrict__ tw, const float* __restrict__ pw,
                             const float* __restrict__ gw, const float* __restrict__ wz)
{
    const int WSZ = IC_ * C_;            // 131072
    int idx = blockIdx.x * 256 + threadIdx.x;
    if (idx < 3 * WSZ) {
        const float* src = (idx < WSZ) ? tw : (idx < 2 * WSZ ? pw : gw);
        g_Wh[idx] = __float2half_rn(src[idx % WSZ]);
    } else {
        int off = idx - 3 * WSZ;
        g_wzh[off] = __float2half_rn(wz[off]);
    }
}

// Prep: x [b][c][n] fp32 -> xh [b][token][c] fp16 (transpose)
__global__ __launch_bounds__(256) void x_to_h(const float* __restrict__ x)
{
    __shared__ float t[32][33];
    const int b  = blockIdx.z;
    const int n0 = blockIdx.x * 32;
    const int c0 = blockIdx.y * 32;
    const float* xb = x + (size_t)b * C_ * N_;
    __half* xh = g_xh + (size_t)b * NP_ * C_;
    const int tx = threadIdx.x, ty = threadIdx.y;

    #pragma unroll
    for (int j = 0; j < 32; j += 8)
        t[ty + j][tx] = xb[(size_t)(c0 + ty + j) * N_ + n0 + tx];
    __syncthreads();
    #pragma unroll
    for (int j = 0; j < 32; j += 8)
        xh[(size_t)(n0 + ty + j) * C_ + c0 + tx] = __float2half_rn(t[tx][ty + j]);
}

// ===========================================================================
// Fused QKV: fp16 mma, 64(m) x 64(n) x 32 double-buffered; one x-tile feeds
// 3 weight tiles. 256 threads, 8 warps all in n (warp tile 64x8 per output).
// Q,K written [token][i]; V written transposed [i][token].
// ===========================================================================
__global__ __launch_bounds__(256) void qkv3_f16(
    const float* __restrict__ tb, const float* __restrict__ pb,
    const float* __restrict__ gb,
    __half* __restrict__ Q, __half* __restrict__ K, __half* __restrict__ Vt)
{
    const long long z = blockIdx.z;
    const __half* xh = g_xh + z * (long long)NP_ * C_;
    Q  += z * (long long)NP_ * IC_;
    K  += z * (long long)NP_ * IC_;
    Vt += z * (long long)IC_ * NP_;

    const int m0 = blockIdx.x * 64;
    const int n0 = blockIdx.y * 64;
    const int tid = threadIdx.x;
    const int w = tid >> 5, lane = tid & 31;
    const int gid = lane >> 2, tig = lane & 3;
    const int wn = w * 8;   // 8 warps x 8 cols = 64

    __shared__ uint32_t Ah[2][64 * FSTR];
    __shared__ uint32_t Bh[2][192 * FSTR];   // 3 weight tiles of 64 rows

    float acc[3][4][4];   // [s][m-tile][reg]
    #pragma unroll
    for (int s = 0; s < 3; s++)
        #pragma unroll
        for (int i = 0; i < 4; i++)
            #pragma unroll
            for (int r = 0; r < 4; r++) acc[s][i][r] = 0.0f;

    uint4 ra, rb[3];
    auto gload = [&](int k0) {
        // A: 64 rows x 4 uint4 = 256 -> 1 per thread
        int row = tid >> 2, k8 = (tid & 3) << 3;
        ra = *(const uint4*)(xh + (long long)(m0 + row) * C_ + k0 + k8);
        // B: 192 rows x 4 uint4 = 768 -> 3 per thread
        #pragma unroll
        for (int it = 0; it < 3; it++) {
            int lin = tid + it * 256;
            int brow = lin >> 2, bk8 = (lin & 3) << 3;
            int s = brow >> 6, wr = brow & 63;
            rb[it] = *(const uint4*)(g_Wh + ((long long)s * IC_ + n0 + wr) * C_ + k0 + bk8);
        }
    };
    auto sstore = [&](int b) {
        int row = tid >> 2, kw = (tid & 3) << 2;
        *(uint4*)(&Ah[b][row * FSTR + kw]) = ra;
        #pragma unroll
        for (int it = 0; it < 3; it++) {
            int lin = tid + it * 256;
            int brow = lin >> 2, bkw = (lin & 3) << 2;
            *(uint4*)(&Bh[b][brow * FSTR + bkw]) = rb[it];
        }
    };

    gload(0); sstore(0); __syncthreads();
    int buf = 0;
    for (int k0 = 0; k0 < C_; k0 += 32) {
        const bool nxt = (k0 + 32 < C_);
        if (nxt) gload(k0 + 32);

        const uint32_t* Ab = Ah[buf];
        const uint32_t* Bb = Bh[buf];
        #pragma unroll
        for (int ks = 0; ks < 2; ks++) {
            const int kc = ks * 8;
            uint32_t af[4][4];
            #pragma unroll
            for (int i = 0; i < 4; i++) {
                int row = i * 16;
                af[i][0] = Ab[(row + gid)     * FSTR + kc + tig];
                af[i][1] = Ab[(row + gid + 8) * FSTR + kc + tig];
                af[i][2] = Ab[(row + gid)     * FSTR + kc + tig + 4];
                af[i][3] = Ab[(row + gid + 8) * FSTR + kc + tig + 4];
            }
            #pragma unroll
            for (int s = 0; s < 3; s++) {
                int col = s * 64 + wn;
                uint32_t b0 = Bb[(col + gid) * FSTR + kc + tig];
                uint32_t b1 = Bb[(col + gid) * FSTR + kc + tig + 4];
                #pragma unroll
                for (int i = 0; i < 4; i++)
                    mma_f16(acc[s][i][0], acc[s][i][1], acc[s][i][2], acc[s][i][3],
                            af[i][0], af[i][1], af[i][2], af[i][3], b0, b1);
            }
        }
        if (nxt) { sstore(buf ^ 1); __syncthreads(); buf ^= 1; }
    }

    // epilogue
    const int gcol = n0 + wn + tig * 2;
    const float tb0 = tb[gcol], tb1 = tb[gcol + 1];
    const float pb0 = pb[gcol], pb1 = pb[gcol + 1];
    const float gb0 = gb[gcol], gb1 = gb[gcol + 1];
    #pragma unroll
    for (int i = 0; i < 4; i++) {
        int grow = m0 + i * 16 + gid;
        *(__half2*)(Q + (long long)grow * IC_ + gcol) =
            __floats2half2_rn(acc[0][i][0] + tb0, acc[0][i][1] + tb1);
        *(__half2*)(Q + (long long)(grow + 8) * IC_ + gcol) =
            __floats2half2_rn(acc[0][i][2] + tb0, acc[0][i][3] + tb1);
        *(__half2*)(K + (long long)grow * IC_ + gcol) =
            __floats2half2_rn(acc[1][i][0] + pb0, acc[1][i][1] + pb1);
        *(__half2*)(K + (long long)(grow + 8) * IC_ + gcol) =
            __floats2half2_rn(acc[1][i][2] + pb0, acc[1][i][3] + pb1);
        Vt[(long long)gcol       * NP_ + grow]     = __float2half_rn(acc[2][i][0] + gb0);
        Vt[(long long)(gcol + 1) * NP_ + grow]     = __float2half_rn(acc[2][i][1] + gb1);
        Vt[(long long)gcol       * NP_ + grow + 8] = __float2half_rn(acc[2][i][2] + gb0);
        Vt[(long long)(gcol + 1) * NP_ + grow + 8] = __float2half_rn(acc[2][i][3] + gb1);
    }
}

// ===========================================================================
// Generic fp16 mma GEMM, 128x128x32 double-buffered. Output fp32 or fp16.
// A [m][k] fp16 k-contig stride sA; B [n][k] fp16 k-contig stride sB.
// ===========================================================================
template<bool HALF_OUT>
__global__ __launch_bounds__(256) void gemm_f16(
    const __half* __restrict__ A, const __half* __restrict__ Bm,
    void* __restrict__ Cc,
    int K, int sA, int sB, int ldc,
    long long batA, long long batB, long long batC)
{
    const long long z = blockIdx.z;
    A  += z * batA;
    Bm += z * batB;

    const int m0 = blockIdx.x * 128;
    const int n0 = blockIdx.y * 128;
    const int tid = threadIdx.x;
    const int w = tid >> 5, lane = tid & 31;
    const int gid = lane >> 2, tig = lane & 3;
    const int wm = (w & 1) * 64, wn = (w >> 1) * 32;

    __shared__ uint32_t As[2][128 * FSTR];
    __shared__ uint32_t Bs[2][128 * FSTR];

    float acc[4][4][4];
    #pragma unroll
    for (int i = 0; i < 4; i++)
        #pragma unroll
        for (int j = 0; j < 4; j++)
            #pragma unroll
            for (int r = 0; r < 4; r++) acc[i][j][r] = 0.0f;

    uint4 ra[2], rb[2];
    auto gload = [&](int k0) {
        #pragma unroll
        for (int it = 0; it < 2; it++) {
            int lin = tid + it * 256;
            int row = lin >> 2, k8 = (lin & 3) << 3;
            ra[it] = *(const uint4*)(A  + (long long)(m0 + row) * sA + k0 + k8);
            rb[it] = *(const uint4*)(Bm + (long long)(n0 + row) * sB + k0 + k8);
        }
    };
    auto sstore = [&](int b) {
        #pragma unroll
        for (int it = 0; it < 2; it++) {
            int lin = tid + it * 256;
            int row = lin >> 2, kw = (lin & 3) << 2;
            *(uint4*)(&As[b][row * FSTR + kw]) = ra[it];
            *(uint4*)(&Bs[b][row * FSTR + kw]) = rb[it];
        }
    };

    gload(0); sstore(0); __syncthreads();
    int buf = 0;
    for (int k0 = 0; k0 < K; k0 += 32) {
        const bool nxt = (k0 + 32 < K);
        if (nxt) gload(k0 + 32);

        const uint32_t* Ab = As[buf];
        const uint32_t* Bb = Bs[buf];
        #pragma unroll
        for (int ks = 0; ks < 2; ks++) {
            const int kc = ks * 8;
            uint32_t af[4][4];
            #pragma unroll
            for (int i = 0; i < 4; i++) {
                int row = wm + i * 16;
                af[i][0] = Ab[(row + gid)     * FSTR + kc + tig];
                af[i][1] = Ab[(row + gid + 8) * FSTR + kc + tig];
                af[i][2] = Ab[(row + gid)     * FSTR + kc + tig + 4];
                af[i][3] = Ab[(row + gid + 8) * FSTR + kc + tig + 4];
            }
            uint32_t bf[4][2];
            #pragma unroll
            for (int j = 0; j < 4; j++) {
                int col = wn + j * 8;
                bf[j][0] = Bb[(col + gid) * FSTR + kc + tig];
                bf[j][1] = Bb[(col + gid) * FSTR + kc + tig + 4];
            }
            #pragma unroll
            for (int i = 0; i < 4; i++)
                #pragma unroll
                for (int j = 0; j < 4; j++)
                    mma_f16(acc[i][j][0], acc[i][j][1], acc[i][j][2], acc[i][j][3],
                            af[i][0], af[i][1], af[i][2], af[i][3],
                            bf[j][0], bf[j][1]);
        }
        if (nxt) { sstore(buf ^ 1); __syncthreads(); buf ^= 1; }
    }

    #pragma unroll
    for (int i = 0; i < 4; i++) {
        int grow = m0 + wm + i * 16 + gid;
        #pragma unroll
        for (int j = 0; j < 4; j++) {
            int gcol = n0 + wn + j * 8 + tig * 2;
            if (HALF_OUT) {
                __half* C = (__half*)Cc + z * batC;
                *(__half2*)(C + (long long)grow * ldc + gcol) =
                    __floats2half2_rn(acc[i][j][0], acc[i][j][1]);
                *(__half2*)(C + (long long)(grow + 8) * ldc + gcol) =
                    __floats2half2_rn(acc[i][j][2], acc[i][j][3]);
            } else {
                float* C = (float*)Cc + z * batC;
                *(float2*)(C + (long long)grow * ldc + gcol) =
                    make_float2(acc[i][j][0], acc[i][j][1]);
                *(float2*)(C + (long long)(grow + 8) * ldc + gcol) =
                    make_float2(acc[i][j][2], acc[i][j][3]);
            }
        }
    }
}

// ===========================================================================
// y2 = y1h * wzh^T + bias, fp16 mma 64x64x32 with fused BN statistics.
// 128 threads, 4 warps 2x2, warp tile 32x32. 8 k-iters, single-buffered.
// ===========================================================================
__global__ __launch_bounds__(128) void y2h_stats(
    const __half* __restrict__ A, const float* __restrict__ bias,
    float* __restrict__ Cc)
{
    const long long z = blockIdx.z;
    A  += z * (long long)NP_ * IC_;
    Cc += z * (long long)N_ * C_;

    const int m0 = blockIdx.x * 64;
    const int n0 = blockIdx.y * 64;
    const int tid = threadIdx.x;
    const int w = tid >> 5, lane = tid & 31;
    const int gid = lane >> 2, tig = lane & 3;
    const int wm = (w & 1) * 32, wn = (w >> 1) * 32;

    __shared__ uint32_t As[64 * FSTR];
    __shared__ uint32_t Bs[64 * FSTR];
    __shared__ float csum[64];
    __shared__ float csq [64];

    if (tid < 64) { csum[tid] = 0.f; csq[tid] = 0.f; }

    float acc[2][4][4];
    #pragma unroll
    for (int i = 0; i < 2; i++)
        #pragma unroll
        for (int j = 0; j < 4; j++)
            #pragma unroll
            for (int r = 0; r < 4; r++) acc[i][j][r] = 0.0f;

    for (int k0 = 0; k0 < IC_; k0 += 32) {
        #pragma unroll
        for (int it = 0; it < 2; it++) {
            int lin = tid + it * 128;
            int row = lin >> 2, k8 = (lin & 3) << 3, kw = (lin & 3) << 2;
            *(uint4*)(&As[row * FSTR + kw]) =
                *(const uint4*)(A + (long long)(m0 + row) * IC_ + k0 + k8);
            *(uint4*)(&Bs[row * FSTR + kw]) =
                *(const uint4*)(g_wzh + (long long)(n0 + row) * IC_ + k0 + k8);
        }
        __syncthreads();

        #pragma unroll
        for (int ks = 0; ks < 2; ks++) {
            const int kc = ks * 8;
            uint32_t af[2][4];
            #pragma unroll
            for (int i = 0; i < 2; i++) {
                int row = wm + i * 16;
                af[i][0] = As[(row + gid)     * FSTR + kc + tig];
                af[i][1] = As[(row + gid + 8) * FSTR + kc + tig];
                af[i][2] = As[(row + gid)     * FSTR + kc + tig + 4];
                af[i][3] = As[(row + gid + 8) * FSTR + kc + tig + 4];
            }
            uint32_t bf[4][2];
            #pragma unroll
            for (int j = 0; j < 4; j++) {
                int col = wn + j * 8;
                bf[j][0] = Bs[(col + gid) * FSTR + kc + tig];
                bf[j][1] = Bs[(col + gid) * FSTR + kc + tig + 4];
            }
            #pragma unroll
            for (int i = 0; i < 2; i++)
                #pragma unroll
                for (int j = 0; j < 4; j++)
                    mma_f16(acc[i][j][0], acc[i][j][1], acc[i][j][2], acc[i][j][3],
                            af[i][0], af[i][1], af[i][2], af[i][3],
                            bf[j][0], bf[j][1]);
        }
        __syncthreads();
    }

    // epilogue: bias + store + per-column stats
    #pragma unroll
    for (int j = 0; j < 4; j++) {
        int lcol = wn + j * 8 + tig * 2;
        int gcol = n0 + lcol;
        float b0v = bias[gcol], b1v = bias[gcol + 1];
        float s0 = 0.f, q0 = 0.f, s1 = 0.f, q1 = 0.f;
        #pragma unroll
        for (int i = 0; i < 2; i++) {
            int grow = m0 + wm + i * 16 + gid;
            float v00 = acc[i][j][0] + b0v;
            float v01 = acc[i][j][1] + b1v;
            float v10 = acc[i][j][2] + b0v;
            float v11 = acc[i][j][3] + b1v;
            *(float2*)(Cc + (long long)grow * C_ + gcol)       = make_float2(v00, v01);
            *(float2*)(Cc + (long long)(grow + 8) * C_ + gcol) = make_float2(v10, v11);
            s0 += v00 + v10;  q0 += v00 * v00 + v10 * v10;
            s1 += v01 + v11;  q1 += v01 * v01 + v11 * v11;
        }
        atomicAdd(&csum[lcol],     s0);
        atomicAdd(&csq [lcol],     q0);
        atomicAdd(&csum[lcol + 1], s1);
        atomicAdd(&csq [lcol + 1], q1);
    }
    __syncthreads();
    if (tid < 64) {
        atomicAdd(&g_sum  [n0 + tid], (double)csum[tid]);
        atomicAdd(&g_sumsq[n0 + tid], (double)csq [tid]);
    }
}

// ---------------------------------------------------------------------------
// Row softmax: float4 + warp shuffles + MUFU exp (unchanged)
// ---------------------------------------------------------------------------
#define NF4 (N_ / 4)   // 784 float4 per row

__global__ __launch_bounds__(256) void softmax_rows(
    const float* __restrict__ S, __half* __restrict__ P)
{
    __shared__ float buf[N_];
    __shared__ float wredm[8];
    __shared__ float wreds[8];
    const float* row = S + (size_t)blockIdx.y * NP_ * NP_ + (size_t)blockIdx.x * NP_;
    __half* prow     = P + (size_t)blockIdx.y * NP_ * NP_ + (size_t)blockIdx.x * NP_;
    const int tid = threadIdx.x;
    const int wid = tid >> 5, lane = tid & 31;

    float m = -1e30f;
    for (int i4 = tid; i4 < NF4; i4 += 256) {
        float4 v = ((const float4*)row)[i4];
        ((float4*)buf)[i4] = v;
        m = fmaxf(fmaxf(m, fmaxf(v.x, v.y)), fmaxf(v.z, v.w));
    }
    #pragma unroll
    for (int o = 16; o > 0; o >>= 1) m = fmaxf(m, __shfl_xor_sync(~0u, m, o));
    if (lane == 0) wredm[wid] = m;
    __syncthreads();
    m = wredm[0];
    #pragma unroll
    for (int k = 1; k < 8; k++) m = fmaxf(m, wredm[k]);

    float sum = 0.f;
    for (int i4 = tid; i4 < NF4; i4 += 256) {
        float4 v = ((const float4*)buf)[i4];
        v.x = __expf(v.x - m); v.y = __expf(v.y - m);
        v.z = __expf(v.z - m); v.w = __expf(v.w - m);
        ((float4*)buf)[i4] = v;
        sum += (v.x + v.y) + (v.z + v.w);
    }
    #pragma unroll
    for (int o = 16; o > 0; o >>= 1) sum += __shfl_xor_sync(~0u, sum, o);
    if (lane == 0) wreds[wid] = sum;
    __syncthreads();
    sum = wreds[0];
    #pragma unroll
    for (int k = 1; k < 8; k++) sum += wreds[k];
    const float inv = 1.0f / sum;

    for (int i4 = tid; i4 < NF4; i4 += 256) {
        float4 v = ((const float4*)buf)[i4];
        uint2 o;
        __half2 h0 = __floats2half2_rn(v.x * inv, v.y * inv);
        __half2 h1 = __floats2half2_rn(v.z * inv, v.w * inv);
        o.x = *(uint32_t*)&h0;
        o.y = *(uint32_t*)&h1;
        ((uint2*)prow)[i4] = o;
    }
}

// ---------------------------------------------------------------------------
// BN: zero stats + final normalize/residual/transpose (unchanged)
// ---------------------------------------------------------------------------
__global__ void zero_stats()
{
    int t = threadIdx.x;   // 512 threads
    g_sum[t] = 0.0;
    g_sumsq[t] = 0.0;
}

__global__ __launch_bounds__(256) void bn_final(
    const float* __restrict__ x,
    const float* __restrict__ bn_w, const float* __restrict__ bn_b,
    float* __restrict__ out)
{
    __shared__ float t[32][33];
    const int b  = blockIdx.z;
    const int c0 = blockIdx.y * 32;
    const int n0 = blockIdx.x * 32;
    const int tx = threadIdx.x, ty = threadIdx.y;

    #pragma unroll
    for (int j = 0; j < 32; j += 8) {
        int n = n0 + ty + j;
        t[ty + j][tx] = g_y2[((size_t)(b * N_ + n)) * C_ + c0 + tx];
    }
    __syncthreads();

    const double cnt = (double)ROWS_TOTAL;
    #pragma unroll
    for (int j = 0; j < 32; j += 8) {
        int c = c0 + ty + j;
        double mean = g_sum[c] / cnt;
        double var  = g_sumsq[c] / cnt - mean * mean;
        float inv = (float)rsqrt(var + 1e-5);
        float w = bn_w[c], bb = bn_b[c];
        int n = n0 + tx;
        size_t oidx = ((size_t)b * C_ + c) * (size_t)N_ + n;
        float v = t[tx][ty + j];
        out[oidx] = (v - (float)mean) * inv * w + bb + x[oidx];
    }
}

// ---------------------------------------------------------------------------
// Launch
// ---------------------------------------------------------------------------
extern "C" void kernel_launch(void* const* d_in, const int* in_sizes, int n_in,
                              void* d_out, int out_size)
{
    const float* x       = (const float*)d_in[0];
    const float* theta_w = (const float*)d_in[1];
    const float* theta_b = (const float*)d_in[2];
    const float* phi_w   = (const float*)d_in[3];
    const float* phi_b   = (const float*)d_in[4];
    const float* gw      = (const float*)d_in[5];
    const float* gb      = (const float*)d_in[6];
    const float* wz_w    = (const float*)d_in[7];
    const float* wz_b    = (const float*)d_in[8];
    const float* bn_w    = (const float*)d_in[9];
    const float* bn_b    = (const float*)d_in[10];
    float* out = (float*)d_out;

    float *S, *y2;
    __half *Qh, *Kh, *Vt, *P, *y1h;
    cudaGetSymbolAddress((void**)&Qh,  g_Qh);
    cudaGetSymbolAddress((void**)&Kh,  g_Kh);
    cudaGetSymbolAddress((void**)&Vt,  g_Vt);
    cudaGetSymbolAddress((void**)&S,   g_S);
    cudaGetSymbolAddress((void**)&P,   g_P);
    cudaGetSymbolAddress((void**)&y1h, g_y1h);
    cudaGetSymbolAddress((void**)&y2,  g_y2);

    zero_stats<<<1, 512>>>();

    // prep: weights -> fp16; x -> fp16 transposed [token][c]
    conv_weights<<<(4 * IC_ * C_) / 256, 256>>>(theta_w, phi_w, gw, wz_w);
    x_to_h<<<dim3(N_ / 32, C_ / 32, B_), dim3(32, 8)>>>(x);

    // fused QKV projections (fp16 mma)
    qkv3_f16<<<dim3(N_ / 64 + 1, IC_ / 64, B_), 256>>>(
        theta_b, phi_b, gb, Qh, Kh, Vt);

    // S = Qh Kh^T (fp16 mma, fp32 out)
    gemm_f16<false><<<dim3(NP_ / 128, NP_ / 128, B_), 256>>>(Qh, Kh, S,
        IC_, IC_, IC_, NP_,
        (long long)NP_ * IC_, (long long)NP_ * IC_, (long long)NP_ * NP_);

    // softmax rows -> fp16 probs
    softmax_rows<<<dim3(N_, B_), 256>>>(S, P);

    // y1 = P Vt^T (fp16 mma, fp16 out)
    gemm_f16<true><<<dim3(NP_ / 128, IC_ / 128, B_), 256>>>(P, Vt, y1h,
        N_, NP_, NP_, IC_,
        (long long)NP_ * NP_, (long long)IC_ * NP_, (long long)NP_ * IC_);

    // y2 = y1h wzh^T + b (fp16 mma) with fused BN statistics
    y2h_stats<<<dim3(N_ / 64, C_ / 64, B_), 128>>>(y1h, wz_b, y2);

    // BN normalize + residual + transpose
    bn_final<<<dim3(N_ / 32, C_ / 32, B_), dim3(32, 8)>>>(x, bn_w, bn_b, out);
}

// round 11
// speedup vs baseline: 3.6823x; 1.0756x over previous
#include <cuda_runtime.h>
#include <cuda_fp16.h>
#include <math.h>
#include <stdint.h>

// Problem constants
#define B_   8
#define C_   512
#define N_   3136   // 56*56
#define NP_  3200   // N padded to multiple of 128
#define IC_  256
#define ROWS_TOTAL (B_ * N_)   // 25088

// ---------------------------------------------------------------------------
// Scratch
// ---------------------------------------------------------------------------
__device__ __half g_xh [(size_t)B_ * NP_ * C_];   // x fp16 transposed [token][c]
__device__ __half g_Wh [(size_t)3 * IC_ * C_];    // theta/phi/g weights fp16
__device__ __half g_wzh[(size_t)C_ * IC_];        // wz fp16
__device__ __half g_Qh [(size_t)B_ * NP_ * IC_];  // Q fp16 [token][i]
__device__ __half g_Kh [(size_t)B_ * NP_ * IC_];  // K fp16 [token][i]
__device__ __half g_Vt [(size_t)B_ * IC_ * NP_];  // V fp16 transposed [i][token]
__device__ float  g_S  [(size_t)B_ * NP_ * NP_];  // logits fp32
__device__ __half g_P  [(size_t)B_ * NP_ * NP_];  // softmax probs fp16
__device__ __half g_y1h[(size_t)B_ * NP_ * IC_];  // attention out fp16
__device__ float  g_y2 [(size_t)B_ * N_ * C_];
__device__ double g_sum[C_];
__device__ double g_sumsq[C_];

// ---------------------------------------------------------------------------
// mma / ldmatrix helpers
// ---------------------------------------------------------------------------
__device__ __forceinline__ void mma_f16(float& d0, float& d1, float& d2, float& d3,
                                        uint32_t a0, uint32_t a1, uint32_t a2, uint32_t a3,
                                        uint32_t b0, uint32_t b1) {
    asm volatile(
        "mma.sync.aligned.m16n8k16.row.col.f32.f16.f16.f32 "
        "{%0,%1,%2,%3}, {%4,%5,%6,%7}, {%8,%9}, {%0,%1,%2,%3};\n"
        : "+f"(d0), "+f"(d1), "+f"(d2), "+f"(d3)
        : "r"(a0), "r"(a1), "r"(a2), "r"(a3), "r"(b0), "r"(b1));
}
__device__ __forceinline__ void ldsm_x4(uint32_t& r0, uint32_t& r1, uint32_t& r2, uint32_t& r3,
                                        uint32_t addr) {
    asm volatile("ldmatrix.sync.aligned.m8n8.x4.shared.b16 {%0,%1,%2,%3}, [%4];"
                 : "=r"(r0), "=r"(r1), "=r"(r2), "=r"(r3) : "r"(addr));
}
__device__ __forceinline__ void ldsm_x2(uint32_t& r0, uint32_t& r1, uint32_t addr) {
    asm volatile("ldmatrix.sync.aligned.m8n8.x2.shared.b16 {%0,%1}, [%2];"
                 : "=r"(r0), "=r"(r1) : "r"(addr));
}
__device__ __forceinline__ uint32_t smem_u32(const void* p) {
    return (uint32_t)__cvta_generic_to_shared(p);
}

constexpr int FSTR = 20;       // 20 words = 80 bytes per SMEM row (32 data halves + pad)
constexpr int FSTRB = 80;      // bytes

// ---------------------------------------------------------------------------
// Prep kernels
// ---------------------------------------------------------------------------
__global__ void conv_weights(const float* __restrict__ tw, const float* __restrict__ pw,
                             const float* __restrict__ gw, const float* __restrict__ wz)
{
    const int WSZ = IC_ * C_;            // 131072
    int idx = blockIdx.x * 256 + threadIdx.x;
    if (idx < 3 * WSZ) {
        const float* src = (idx < WSZ) ? tw : (idx < 2 * WSZ ? pw : gw);
        g_Wh[idx] = __float2half_rn(src[idx % WSZ]);
    } else {
        int off = idx - 3 * WSZ;
        g_wzh[off] = __float2half_rn(wz[off]);
    }
}

__global__ __launch_bounds__(256) void x_to_h(const float* __restrict__ x)
{
    __shared__ float t[32][33];
    const int b  = blockIdx.z;
    const int n0 = blockIdx.x * 32;
    const int c0 = blockIdx.y * 32;
    const float* xb = x + (size_t)b * C_ * N_;
    __half* xh = g_xh + (size_t)b * NP_ * C_;
    const int tx = threadIdx.x, ty = threadIdx.y;

    #pragma unroll
    for (int j = 0; j < 32; j += 8)
        t[ty + j][tx] = xb[(size_t)(c0 + ty + j) * N_ + n0 + tx];
    __syncthreads();
    #pragma unroll
    for (int j = 0; j < 32; j += 8)
        xh[(size_t)(n0 + ty + j) * C_ + c0 + tx] = __float2half_rn(t[tx][ty + j]);
}

// ===========================================================================
// Fused QKV: fp16 mma + ldmatrix, 64(m) x 64(n) x 32 double-buffered.
// 8 warps in n (warp tile 64x8 per output matrix).
// ===========================================================================
__global__ __launch_bounds__(256) void qkv3_f16(
    const float* __restrict__ tb, const float* __restrict__ pb,
    const float* __restrict__ gb,
    __half* __restrict__ Q, __half* __restrict__ K, __half* __restrict__ Vt)
{
    const long long z = blockIdx.z;
    const __half* xh = g_xh + z * (long long)NP_ * C_;
    Q  += z * (long long)NP_ * IC_;
    K  += z * (long long)NP_ * IC_;
    Vt += z * (long long)IC_ * NP_;

    const int m0 = blockIdx.x * 64;
    const int n0 = blockIdx.y * 64;
    const int tid = threadIdx.x;
    const int w = tid >> 5, lane = tid & 31;
    const int gid = lane >> 2, tig = lane & 3;
    const int wn = w * 8;

    __shared__ uint32_t Ah[2][64 * FSTR];
    __shared__ uint32_t Bh[2][192 * FSTR];

    // ldmatrix lane-address components
    const int a_row = (lane & 7) + ((lane >> 3) & 1) * 8;   // row within 16
    const int a_kb  = (lane >> 4) * 16;                      // k byte offset (0/16)
    const int b_row = (lane & 7);                            // x2: lanes 0-15 used
    const int b_kb  = (((lane & 15) >> 3) & 1) * 16;

    float acc[3][4][4];
    #pragma unroll
    for (int s = 0; s < 3; s++)
        #pragma unroll
        for (int i = 0; i < 4; i++)
            #pragma unroll
            for (int r = 0; r < 4; r++) acc[s][i][r] = 0.0f;

    uint4 ra, rb[3];
    auto gload = [&](int k0) {
        int row = tid >> 2, k8 = (tid & 3) << 3;
        ra = *(const uint4*)(xh + (long long)(m0 + row) * C_ + k0 + k8);
        #pragma unroll
        for (int it = 0; it < 3; it++) {
            int lin = tid + it * 256;
            int brow = lin >> 2, bk8 = (lin & 3) << 3;
            int s = brow >> 6, wr = brow & 63;
            rb[it] = *(const uint4*)(g_Wh + ((long long)s * IC_ + n0 + wr) * C_ + k0 + bk8);
        }
    };
    auto sstore = [&](int b) {
        int row = tid >> 2, kw = (tid & 3) << 2;
        *(uint4*)(&Ah[b][row * FSTR + kw]) = ra;
        #pragma unroll
        for (int it = 0; it < 3; it++) {
            int lin = tid + it * 256;
            int brow = lin >> 2, bkw = (lin & 3) << 2;
            *(uint4*)(&Bh[b][brow * FSTR + bkw]) = rb[it];
        }
    };

    gload(0); sstore(0); __syncthreads();
    int buf = 0;
    for (int k0 = 0; k0 < C_; k0 += 32) {
        const bool nxt = (k0 + 32 < C_);
        if (nxt) gload(k0 + 32);

        const uint32_t abase = smem_u32(Ah[buf]);
        const uint32_t bbase = smem_u32(Bh[buf]);
        #pragma unroll
        for (int ks = 0; ks < 2; ks++) {
            const int kb = ks * 32;   // byte offset of k-block (8 words = 32B)
            uint32_t af[4][4];
            #pragma unroll
            for (int i = 0; i < 4; i++)
                ldsm_x4(af[i][0], af[i][1], af[i][2], af[i][3],
                        abase + (i * 16 + a_row) * FSTRB + kb + a_kb);
            #pragma unroll
            for (int s = 0; s < 3; s++) {
                uint32_t b0, b1;
                ldsm_x2(b0, b1,
                        bbase + (s * 64 + wn + b_row) * FSTRB + kb + b_kb);
                #pragma unroll
                for (int i = 0; i < 4; i++)
                    mma_f16(acc[s][i][0], acc[s][i][1], acc[s][i][2], acc[s][i][3],
                            af[i][0], af[i][1], af[i][2], af[i][3], b0, b1);
            }
        }
        if (nxt) { sstore(buf ^ 1); __syncthreads(); buf ^= 1; }
    }

    const int gcol = n0 + wn + tig * 2;
    const float tb0 = tb[gcol], tb1 = tb[gcol + 1];
    const float pb0 = pb[gcol], pb1 = pb[gcol + 1];
    const float gb0 = gb[gcol], gb1 = gb[gcol + 1];
    #pragma unroll
    for (int i = 0; i < 4; i++) {
        int grow = m0 + i * 16 + gid;
        *(__half2*)(Q + (long long)grow * IC_ + gcol) =
            __floats2half2_rn(acc[0][i][0] + tb0, acc[0][i][1] + tb1);
        *(__half2*)(Q + (long long)(grow + 8) * IC_ + gcol) =
            __floats2half2_rn(acc[0][i][2] + tb0, acc[0][i][3] + tb1);
        *(__half2*)(K + (long long)grow * IC_ + gcol) =
            __floats2half2_rn(acc[1][i][0] + pb0, acc[1][i][1] + pb1);
        *(__half2*)(K + (long long)(grow + 8) * IC_ + gcol) =
            __floats2half2_rn(acc[1][i][2] + pb0, acc[1][i][3] + pb1);
        Vt[(long long)gcol       * NP_ + grow]     = __float2half_rn(acc[2][i][0] + gb0);
        Vt[(long long)(gcol + 1) * NP_ + grow]     = __float2half_rn(acc[2][i][1] + gb1);
        Vt[(long long)gcol       * NP_ + grow + 8] = __float2half_rn(acc[2][i][2] + gb0);
        Vt[(long long)(gcol + 1) * NP_ + grow + 8] = __float2half_rn(acc[2][i][3] + gb1);
    }
}

// ===========================================================================
// Generic fp16 mma GEMM + ldmatrix, 128x128x32 double-buffered.
// ===========================================================================
template<bool HALF_OUT>
__global__ __launch_bounds__(256) void gemm_f16(
    const __half* __restrict__ A, const __half* __restrict__ Bm,
    void* __restrict__ Cc,
    int K, int sA, int sB, int ldc,
    long long batA, long long batB, long long batC)
{
    const long long z = blockIdx.z;
    A  += z * batA;
    Bm += z * batB;

    const int m0 = blockIdx.x * 128;
    const int n0 = blockIdx.y * 128;
    const int tid = threadIdx.x;
    const int w = tid >> 5, lane = tid & 31;
    const int gid = lane >> 2, tig = lane & 3;
    const int wm = (w & 1) * 64, wn = (w >> 1) * 32;

    __shared__ uint32_t As[2][128 * FSTR];
    __shared__ uint32_t Bs[2][128 * FSTR];

    const int a_row = (lane & 7) + ((lane >> 3) & 1) * 8;
    const int a_kb  = (lane >> 4) * 16;
    const int b_row = (lane & 7) + (lane >> 4) * 8;          // x4 B-pair: n row
    const int b_kb  = ((lane >> 3) & 1) * 16;

    float acc[4][4][4];
    #pragma unroll
    for (int i = 0; i < 4; i++)
        #pragma unroll
        for (int j = 0; j < 4; j++)
            #pragma unroll
            for (int r = 0; r < 4; r++) acc[i][j][r] = 0.0f;

    uint4 ra[2], rb[2];
    auto gload = [&](int k0) {
        #pragma unroll
        for (int it = 0; it < 2; it++) {
            int lin = tid + it * 256;
            int row = lin >> 2, k8 = (lin & 3) << 3;
            ra[it] = *(const uint4*)(A  + (long long)(m0 + row) * sA + k0 + k8);
            rb[it] = *(const uint4*)(Bm + (long long)(n0 + row) * sB + k0 + k8);
        }
    };
    auto sstore = [&](int b) {
        #pragma unroll
        for (int it = 0; it < 2; it++) {
            int lin = tid + it * 256;
            int row = lin >> 2, kw = (lin & 3) << 2;
            *(uint4*)(&As[b][row * FSTR + kw]) = ra[it];
            *(uint4*)(&Bs[b][row * FSTR + kw]) = rb[it];
        }
    };

    gload(0); sstore(0); __syncthreads();
    int buf = 0;
    for (int k0 = 0; k0 < K; k0 += 32) {
        const bool nxt = (k0 + 32 < K);
        if (nxt) gload(k0 + 32);

        const uint32_t abase = smem_u32(As[buf]);
        const uint32_t bbase = smem_u32(Bs[buf]);
        #pragma unroll
        for (int ks = 0; ks < 2; ks++) {
            const int kb = ks * 32;
            uint32_t af[4][4];
            #pragma unroll
            for (int i = 0; i < 4; i++)
                ldsm_x4(af[i][0], af[i][1], af[i][2], af[i][3],
                        abase + (wm + i * 16 + a_row) * FSTRB + kb + a_kb);
            uint32_t bf[4][2];
            #pragma unroll
            for (int jj = 0; jj < 2; jj++)
                ldsm_x4(bf[jj * 2][0], bf[jj * 2][1], bf[jj * 2 + 1][0], bf[jj * 2 + 1][1],
                        bbase + (wn + jj * 16 + b_row) * FSTRB + kb + b_kb);
            #pragma unroll
            for (int i = 0; i < 4; i++)
                #pragma unroll
                for (int j = 0; j < 4; j++)
                    mma_f16(acc[i][j][0], acc[i][j][1], acc[i][j][2], acc[i][j][3],
                            af[i][0], af[i][1], af[i][2], af[i][3],
                            bf[j][0], bf[j][1]);
        }
        if (nxt) { sstore(buf ^ 1); __syncthreads(); buf ^= 1; }
    }

    #pragma unroll
    for (int i = 0; i < 4; i++) {
        int grow = m0 + wm + i * 16 + gid;
        #pragma unroll
        for (int j = 0; j < 4; j++) {
            int gcol = n0 + wn + j * 8 + tig * 2;
            if (HALF_OUT) {
                __half* C = (__half*)Cc + z * batC;
                *(__half2*)(C + (long long)grow * ldc + gcol) =
                    __floats2half2_rn(acc[i][j][0], acc[i][j][1]);
                *(__half2*)(C + (long long)(grow + 8) * ldc + gcol) =
                    __floats2half2_rn(acc[i][j][2], acc[i][j][3]);
            } else {
                float* C = (float*)Cc + z * batC;
                *(float2*)(C + (long long)grow * ldc + gcol) =
                    make_float2(acc[i][j][0], acc[i][j][1]);
                *(float2*)(C + (long long)(grow + 8) * ldc + gcol) =
                    make_float2(acc[i][j][2], acc[i][j][3]);
            }
        }
    }
}

// ===========================================================================
// y2 = y1h * wzh^T + bias, fp16 mma + ldmatrix, 64x64x32 with fused BN stats
// ===========================================================================
__global__ __launch_bounds__(128) void y2h_stats(
    const __half* __restrict__ A, const float* __restrict__ bias,
    float* __restrict__ Cc)
{
    const long long z = blockIdx.z;
    A  += z * (long long)NP_ * IC_;
    Cc += z * (long long)N_ * C_;

    const int m0 = blockIdx.x * 64;
    const int n0 = blockIdx.y * 64;
    const int tid = threadIdx.x;
    const int w = tid >> 5, lane = tid & 31;
    const int gid = lane >> 2, tig = lane & 3;
    const int wm = (w & 1) * 32, wn = (w >> 1) * 32;

    __shared__ uint32_t As[64 * FSTR];
    __shared__ uint32_t Bs[64 * FSTR];
    __shared__ float csum[64];
    __shared__ float csq [64];

    if (tid < 64) { csum[tid] = 0.f; csq[tid] = 0.f; }

    const int a_row = (lane & 7) + ((lane >> 3) & 1) * 8;
    const int a_kb  = (lane >> 4) * 16;
    const int b_row = (lane & 7) + (lane >> 4) * 8;
    const int b_kb  = ((lane >> 3) & 1) * 16;

    float acc[2][4][4];
    #pragma unroll
    for (int i = 0; i < 2; i++)
        #pragma unroll
        for (int j = 0; j < 4; j++)
            #pragma unroll
            for (int r = 0; r < 4; r++) acc[i][j][r] = 0.0f;

    for (int k0 = 0; k0 < IC_; k0 += 32) {
        #pragma unroll
        for (int it = 0; it < 2; it++) {
            int lin = tid + it * 128;
            int row = lin >> 2, k8 = (lin & 3) << 3, kw = (lin & 3) << 2;
            *(uint4*)(&As[row * FSTR + kw]) =
                *(const uint4*)(A + (long long)(m0 + row) * IC_ + k0 + k8);
            *(uint4*)(&Bs[row * FSTR + kw]) =
                *(const uint4*)(g_wzh + (long long)(n0 + row) * IC_ + k0 + k8);
        }
        __syncthreads();

        const uint32_t abase = smem_u32(As);
        const uint32_t bbase = smem_u32(Bs);
        #pragma unroll
        for (int ks = 0; ks < 2; ks++) {
            const int kb = ks * 32;
            uint32_t af[2][4];
            #pragma unroll
            for (int i = 0; i < 2; i++)
                ldsm_x4(af[i][0], af[i][1], af[i][2], af[i][3],
                        abase + (wm + i * 16 + a_row) * FSTRB + kb + a_kb);
            uint32_t bf[4][2];
            #pragma unroll
            for (int jj = 0; jj < 2; jj++)
                ldsm_x4(bf[jj * 2][0], bf[jj * 2][1], bf[jj * 2 + 1][0], bf[jj * 2 + 1][1],
                        bbase + (wn + jj * 16 + b_row) * FSTRB + kb + b_kb);
            #pragma unroll
            for (int i = 0; i < 2; i++)
                #pragma unroll
                for (int j = 0; j < 4; j++)
                    mma_f16(acc[i][j][0], acc[i][j][1], acc[i][j][2], acc[i][j][3],
                            af[i][0], af[i][1], af[i][2], af[i][3],
                            bf[j][0], bf[j][1]);
        }
        __syncthreads();
    }

    #pragma unroll
    for (int j = 0; j < 4; j++) {
        int lcol = wn + j * 8 + tig * 2;
        int gcol = n0 + lcol;
        float b0v = bias[gcol], b1v = bias[gcol + 1];
        float s0 = 0.f, q0 = 0.f, s1 = 0.f, q1 = 0.f;
        #pragma unroll
        for (int i = 0; i < 2; i++) {
            int grow = m0 + wm + i * 16 + gid;
            float v00 = acc[i][j][0] + b0v;
            float v01 = acc[i][j][1] + b1v;
            float v10 = acc[i][j][2] + b0v;
            float v11 = acc[i][j][3] + b1v;
            *(float2*)(Cc + (long long)grow * C_ + gcol)       = make_float2(v00, v01);
            *(float2*)(Cc + (long long)(grow + 8) * C_ + gcol) = make_float2(v10, v11);
            s0 += v00 + v10;  q0 += v00 * v00 + v10 * v10;
            s1 += v01 + v11;  q1 += v01 * v01 + v11 * v11;
        }
        atomicAdd(&csum[lcol],     s0);
        atomicAdd(&csq [lcol],     q0);
        atomicAdd(&csum[lcol + 1], s1);
        atomicAdd(&csq [lcol + 1], q1);
    }
    __syncthreads();
    if (tid < 64) {
        atomicAdd(&g_sum  [n0 + tid], (double)csum[tid]);
        atomicAdd(&g_sumsq[n0 + tid], (double)csq [tid]);
    }
}

// ---------------------------------------------------------------------------
// Row softmax (unchanged)
// ---------------------------------------------------------------------------
#define NF4 (N_ / 4)

__global__ __launch_bounds__(256) void softmax_rows(
    const float* __restrict__ S, __half* __restrict__ P)
{
    __shared__ float buf[N_];
    __shared__ float wredm[8];
    __shared__ float wreds[8];
    const float* row = S + (size_t)blockIdx.y * NP_ * NP_ + (size_t)blockIdx.x * NP_;
    __half* prow     = P + (size_t)blockIdx.y * NP_ * NP_ + (size_t)blockIdx.x * NP_;
    const int tid = threadIdx.x;
    const int wid = tid >> 5, lane = tid & 31;

    float m = -1e30f;
    for (int i4 = tid; i4 < NF4; i4 += 256) {
        float4 v = ((const float4*)row)[i4];
        ((float4*)buf)[i4] = v;
        m = fmaxf(fmaxf(m, fmaxf(v.x, v.y)), fmaxf(v.z, v.w));
    }
    #pragma unroll
    for (int o = 16; o > 0; o >>= 1) m = fmaxf(m, __shfl_xor_sync(~0u, m, o));
    if (lane == 0) wredm[wid] = m;
    __syncthreads();
    m = wredm[0];
    #pragma unroll
    for (int k = 1; k < 8; k++) m = fmaxf(m, wredm[k]);

    float sum = 0.f;
    for (int i4 = tid; i4 < NF4; i4 += 256) {
        float4 v = ((const float4*)buf)[i4];
        v.x = __expf(v.x - m); v.y = __expf(v.y - m);
        v.z = __expf(v.z - m); v.w = __expf(v.w - m);
        ((float4*)buf)[i4] = v;
        sum += (v.x + v.y) + (v.z + v.w);
    }
    #pragma unroll
    for (int o = 16; o > 0; o >>= 1) sum += __shfl_xor_sync(~0u, sum, o);
    if (lane == 0) wreds[wid] = sum;
    __syncthreads();
    sum = wreds[0];
    #pragma unroll
    for (int k = 1; k < 8; k++) sum += wreds[k];
    const float inv = 1.0f / sum;

    for (int i4 = tid; i4 < NF4; i4 += 256) {
        float4 v = ((const float4*)buf)[i4];
        uint2 o;
        __half2 h0 = __floats2half2_rn(v.x * inv, v.y * inv);
        __half2 h1 = __floats2half2_rn(v.z * inv, v.w * inv);
        o.x = *(uint32_t*)&h0;
        o.y = *(uint32_t*)&h1;
        ((uint2*)prow)[i4] = o;
    }
}

// ---------------------------------------------------------------------------
// BN: zero stats + final (unchanged)
// ---------------------------------------------------------------------------
__global__ void zero_stats()
{
    int t = threadIdx.x;
    g_sum[t] = 0.0;
    g_sumsq[t] = 0.0;
}

__global__ __launch_bounds__(256) void bn_final(
    const float* __restrict__ x,
    const float* __restrict__ bn_w, const float* __restrict__ bn_b,
    float* __restrict__ out)
{
    __shared__ float t[32][33];
    const int b  = blockIdx.z;
    const int c0 = blockIdx.y * 32;
    const int n0 = blockIdx.x * 32;
    const int tx = threadIdx.x, ty = threadIdx.y;

    #pragma unroll
    for (int j = 0; j < 32; j += 8) {
        int n = n0 + ty + j;
        t[ty + j][tx] = g_y2[((size_t)(b * N_ + n)) * C_ + c0 + tx];
    }
    __syncthreads();

    const double cnt = (double)ROWS_TOTAL;
    #pragma unroll
    for (int j = 0; j < 32; j += 8) {
        int c = c0 + ty + j;
        double mean = g_sum[c] / cnt;
        double var  = g_sumsq[c] / cnt - mean * mean;
        float inv = (float)rsqrt(var + 1e-5);
        float w = bn_w[c], bb = bn_b[c];
        int n = n0 + tx;
        size_t oidx = ((size_t)b * C_ + c) * (size_t)N_ + n;
        float v = t[tx][ty + j];
        out[oidx] = (v - (float)mean) * inv * w + bb + x[oidx];
    }
}

// ---------------------------------------------------------------------------
// Launch
// ---------------------------------------------------------------------------
extern "C" void kernel_launch(void* const* d_in, const int* in_sizes, int n_in,
                              void* d_out, int out_size)
{
    const float* x       = (const float*)d_in[0];
    const float* theta_w = (const float*)d_in[1];
    const float* theta_b = (const float*)d_in[2];
    const float* phi_w   = (const float*)d_in[3];
    const float* phi_b   = (const float*)d_in[4];
    const float* gw      = (const float*)d_in[5];
    const float* gb      = (const float*)d_in[6];
    const float* wz_w    = (const float*)d_in[7];
    const float* wz_b    = (const float*)d_in[8];
    const float* bn_w    = (const float*)d_in[9];
    const float* bn_b    = (const float*)d_in[10];
    float* out = (float*)d_out;

    float *S, *y2;
    __half *Qh, *Kh, *Vt, *P, *y1h;
    cudaGetSymbolAddress((void**)&Qh,  g_Qh);
    cudaGetSymbolAddress((void**)&Kh,  g_Kh);
    cudaGetSymbolAddress((void**)&Vt,  g_Vt);
    cudaGetSymbolAddress((void**)&S,   g_S);
    cudaGetSymbolAddress((void**)&P,   g_P);
    cudaGetSymbolAddress((void**)&y1h, g_y1h);
    cudaGetSymbolAddress((void**)&y2,  g_y2);

    zero_stats<<<1, 512>>>();

    conv_weights<<<(4 * IC_ * C_) / 256, 256>>>(theta_w, phi_w, gw, wz_w);
    x_to_h<<<dim3(N_ / 32, C_ / 32, B_), dim3(32, 8)>>>(x);

    qkv3_f16<<<dim3(N_ / 64 + 1, IC_ / 64, B_), 256>>>(
        theta_b, phi_b, gb, Qh, Kh, Vt);

    gemm_f16<false><<<dim3(NP_ / 128, NP_ / 128, B_), 256>>>(Qh, Kh, S,
        IC_, IC_, IC_, NP_,
        (long long)NP_ * IC_, (long long)NP_ * IC_, (long long)NP_ * NP_);

    softmax_rows<<<dim3(N_, B_), 256>>>(S, P);

    gemm_f16<true><<<dim3(NP_ / 128, IC_ / 128, B_), 256>>>(P, Vt, y1h,
        N_, NP_, NP_, IC_,
        (long long)NP_ * NP_, (long long)IC_ * NP_, (long long)NP_ * IC_);

    y2h_stats<<<dim3(N_ / 64, C_ / 64, B_), 128>>>(y1h, wz_b, y2);

    bn_final<<<dim3(N_ / 32, C_ / 32, B_), dim3(32, 8)>>>(x, bn_w, bn_b, out);
}